// round 2
// baseline (speedup 1.0000x reference)
#include <cuda_runtime.h>
#include <math.h>

#define NB 4
#define NS 1024
#define NH 16
#define HD 64
#define BH (NB*NH)
#define N3 3072

// scratch (static device arrays; no runtime allocation)
__device__ float g_qkv[NB*NS*N3];     // [4096][3072]
__device__ float g_Q[BH*HD*NS];       // [bh][d][s]
__device__ float g_K[BH*HD*NS];       // [bh][d][s]
__device__ float g_V[BH*NS*HD];       // [bh][s][d]
__device__ float g_R[BH*NS*256];      // [(bh*1024+q)][256] rel-bias per q
__device__ float g_AO[BH*NS*HD];      // [bh][s][d]

// ---------------- GEMM1: qkv = x @ w_qkv + b  (4096x3072x1024) ----------------
__global__ __launch_bounds__(256, 2)
void k_gemm_qkv(const float* __restrict__ X, const float* __restrict__ W,
                const float* __restrict__ bias) {
    const int K = 1024, N = N3;
    __shared__ float As[16][132];
    __shared__ float Bs[16][128];
    int t = threadIdx.x, tx = t & 15, ty = t >> 4;
    int m0 = blockIdx.y * 128, n0 = blockIdx.x * 128;
    float acc[8][8];
#pragma unroll
    for (int i = 0; i < 8; i++)
#pragma unroll
        for (int j = 0; j < 8; j++) acc[i][j] = 0.f;
    int ar = t >> 2, ac = (t & 3) << 2;
    int br = t >> 5, bc = (t & 31) << 2;
    const float* Xp = X + (m0 + ar) * K + ac;
    const float* Wp = W + br * N + n0 + bc;
    for (int k0 = 0; k0 < K; k0 += 16) {
        float4 a0 = *(const float4*)(Xp + k0);
        float4 a1 = *(const float4*)(Xp + 64 * K + k0);
        As[ac+0][ar]    = a0.x; As[ac+1][ar]    = a0.y; As[ac+2][ar]    = a0.z; As[ac+3][ar]    = a0.w;
        As[ac+0][ar+64] = a1.x; As[ac+1][ar+64] = a1.y; As[ac+2][ar+64] = a1.z; As[ac+3][ar+64] = a1.w;
        *(float4*)&Bs[br  ][bc] = *(const float4*)(Wp + k0 * N);
        *(float4*)&Bs[br+8][bc] = *(const float4*)(Wp + (k0 + 8) * N);
        __syncthreads();
#pragma unroll
        for (int kk = 0; kk < 16; kk++) {
            float a[8], b[8];
            *(float4*)&a[0] = *(const float4*)&As[kk][ty*8];
            *(float4*)&a[4] = *(const float4*)&As[kk][ty*8+4];
            *(float4*)&b[0] = *(const float4*)&Bs[kk][tx*8];
            *(float4*)&b[4] = *(const float4*)&Bs[kk][tx*8+4];
#pragma unroll
            for (int i = 0; i < 8; i++)
#pragma unroll
                for (int j = 0; j < 8; j++) acc[i][j] += a[i] * b[j];
        }
        __syncthreads();
    }
#pragma unroll
    for (int i = 0; i < 8; i++) {
        float* cp = g_qkv + (m0 + ty*8 + i) * N + n0 + tx*8;
        const float* bp = bias + n0 + tx*8;
        float4 v0, v1;
        v0.x = acc[i][0]+bp[0]; v0.y = acc[i][1]+bp[1]; v0.z = acc[i][2]+bp[2]; v0.w = acc[i][3]+bp[3];
        v1.x = acc[i][4]+bp[4]; v1.y = acc[i][5]+bp[5]; v1.z = acc[i][6]+bp[6]; v1.w = acc[i][7]+bp[7];
        *(float4*)cp = v0; *(float4*)(cp + 4) = v1;
    }
}

// ---------------- repack qkv -> Q[bh][d][s], K[bh][d][s], V[bh][s][d] ----------------
// hidden index = d*16 + h (head fastest)
__global__ __launch_bounds__(256)
void k_repack() {
    __shared__ float smem[64][68];
    int t = threadIdx.x;
    int c0 = blockIdx.x * 64, s0 = blockIdx.y * 64, b = blockIdx.z;
#pragma unroll
    for (int p = 0; p < 4; p++) {
        int lin = t + p * 256;
        int s = lin >> 4, c4 = (lin & 15) << 2;
        *(float4*)&smem[s][c4] = *(const float4*)&g_qkv[(b*1024 + s0 + s)*N3 + c0 + c4];
    }
    __syncthreads();
    int chunk = c0 >> 10;           // 0=Q 1=K 2=V
    int cw = c0 & 1023;
    int dB = cw >> 4;               // base d (4 d values per 64-col tile)
    if (chunk < 2) {
        float* out = (chunk == 0) ? g_Q : g_K;
#pragma unroll
        for (int p = 0; p < 16; p++) {
            int w = t + p * 256;
            int cc = w >> 6, ss = w & 63;
            int d = dB + (cc >> 4), h = cc & 15;
            out[((b*16 + h)*64 + d)*1024 + s0 + ss] = smem[ss][cc];
        }
    } else {
#pragma unroll
        for (int p = 0; p < 4; p++) {
            int w = t + p * 256;
            int h = w >> 6, ss = w & 63;
            float4 v;
            v.x = smem[ss][h]; v.y = smem[ss][16+h]; v.z = smem[ss][32+h]; v.w = smem[ss][48+h];
            *(float4*)&g_V[((b*16 + h)*1024 + s0 + ss)*64 + dB] = v;
        }
    }
}

// ---------------- R[bh*1024+s, j] = sum_d Q[bh][d][s] * rel[j][d], j<255 ----------------
__global__ __launch_bounds__(256)
void k_gemm_rel(const float* __restrict__ rel) {
    extern __shared__ float sm[];
    float* As   = sm;              // [d][s] stride 68
    float* RelT = sm + 64*68;      // [d][j] stride 260
    int t = threadIdx.x, tx = t & 31, ty = t >> 5;
    int mt = blockIdx.x;
    int bh = mt >> 4, s0 = (mt & 15) << 6;
#pragma unroll
    for (int p = 0; p < 4; p++) {
        int lin = t + p * 256;
        int d = lin >> 4, c4 = (lin & 15) << 2;
        *(float4*)&As[d*68 + c4] = *(const float4*)&g_Q[(bh*64 + d)*1024 + s0 + c4];
    }
    for (int e = t; e < 255*64; e += 256) {
        int j = e >> 6, d = e & 63;
        RelT[d*260 + j] = rel[e];
    }
    if (t < 64) RelT[t*260 + 255] = 0.f;
    __syncthreads();
    float acc[8][8];
#pragma unroll
    for (int i = 0; i < 8; i++)
#pragma unroll
        for (int j = 0; j < 8; j++) acc[i][j] = 0.f;
#pragma unroll 16
    for (int d = 0; d < 64; d++) {
        float a[8], bb[8];
        *(float4*)&a[0]  = *(const float4*)&As[d*68 + ty*8];
        *(float4*)&a[4]  = *(const float4*)&As[d*68 + ty*8 + 4];
        *(float4*)&bb[0] = *(const float4*)&RelT[d*260 + tx*8];
        *(float4*)&bb[4] = *(const float4*)&RelT[d*260 + tx*8 + 4];
#pragma unroll
        for (int i = 0; i < 8; i++)
#pragma unroll
            for (int j = 0; j < 8; j++) acc[i][j] += a[i] * bb[j];
    }
#pragma unroll
    for (int i = 0; i < 8; i++) {
        float* rp = g_R + (mt*64 + ty*8 + i)*256 + tx*8;
        *(float4*)rp       = make_float4(acc[i][0], acc[i][1], acc[i][2], acc[i][3]);
        *(float4*)(rp + 4) = make_float4(acc[i][4], acc[i][5], acc[i][6], acc[i][7]);
    }
}

// ---------------- flash attention per (bh, q-tile 64) ----------------
__global__ __launch_bounds__(256, 1)
void k_attn(const int* __restrict__ mask) {
    extern __shared__ float sm[];
    float* QsT = sm;               // [d][q] s68
    float* KsT = sm + 64*68;       // [d][k] s68
    float* Vs  = sm + 2*64*68;     // [k][d] s68
    float* Ps  = sm + 3*64*68;     // [q][k] s68
    float* Rs  = sm + 4*64*68;     // [q][256]
    int t = threadIdx.x, tx = t & 15, ty = t >> 4;
    int qt = blockIdx.x, bh = blockIdx.y;
    int b = bh >> 4, q0 = qt << 6;
#pragma unroll
    for (int p = 0; p < 4; p++) {
        int lin = t + p * 256;
        int d = lin >> 4, c4 = (lin & 15) << 2;
        *(float4*)&QsT[d*68 + c4] = *(const float4*)&g_Q[(bh*64 + d)*1024 + q0 + c4];
    }
#pragma unroll
    for (int p = 0; p < 16; p++) {
        int lin = t + p * 256;
        int q = lin >> 6, j4 = (lin & 63) << 2;
        *(float4*)&Rs[q*256 + j4] = *(const float4*)&g_R[(bh*1024 + q0 + q)*256 + j4];
    }
    float m_i[4], l_i[4], o[4][4];
#pragma unroll
    for (int i = 0; i < 4; i++) {
        m_i[i] = -INFINITY; l_i[i] = 0.f;
#pragma unroll
        for (int j = 0; j < 4; j++) o[i][j] = 0.f;
    }
    __syncthreads();
    for (int kt = 0; kt < 16; kt++) {
#pragma unroll
        for (int p = 0; p < 4; p++) {
            int lin = t + p * 256;
            int r = lin >> 4, c4 = (lin & 15) << 2;
            *(float4*)&KsT[r*68 + c4] = *(const float4*)&g_K[(bh*64 + r)*1024 + kt*64 + c4];
            *(float4*)&Vs [r*68 + c4] = *(const float4*)&g_V[(bh*1024 + kt*64 + r)*64 + c4];
        }
        __syncthreads();
        float s4[4][4];
#pragma unroll
        for (int i = 0; i < 4; i++)
#pragma unroll
            for (int j = 0; j < 4; j++) s4[i][j] = 0.f;
#pragma unroll 16
        for (int d = 0; d < 64; d++) {
            float4 aq = *(const float4*)&QsT[d*68 + ty*4];
            float4 bk = *(const float4*)&KsT[d*68 + tx*4];
            s4[0][0] += aq.x*bk.x; s4[0][1] += aq.x*bk.y; s4[0][2] += aq.x*bk.z; s4[0][3] += aq.x*bk.w;
            s4[1][0] += aq.y*bk.x; s4[1][1] += aq.y*bk.y; s4[1][2] += aq.y*bk.z; s4[1][3] += aq.y*bk.w;
            s4[2][0] += aq.z*bk.x; s4[2][1] += aq.z*bk.y; s4[2][2] += aq.z*bk.z; s4[2][3] += aq.z*bk.w;
            s4[3][0] += aq.w*bk.x; s4[3][1] += aq.w*bk.y; s4[3][2] += aq.w*bk.z; s4[3][3] += aq.w*bk.w;
        }
        int kg0 = kt*64 + tx*4;
#pragma unroll
        for (int i = 0; i < 4; i++) {
            int qg = q0 + ty*4 + i;
            int4 mv = *(const int4*)&mask[(b*1024 + qg)*1024 + kg0];
            int mm[4] = {mv.x, mv.y, mv.z, mv.w};
            float sv[4];
#pragma unroll
            for (int j = 0; j < 4; j++) {
                int r = kg0 + j - qg;
                r = min(127, max(-127, r));
                float v = 8.0f * s4[i][j] + Rs[(ty*4 + i)*256 + r + 127];
                sv[j] = (mm[j] == 0) ? -1e8f : v;
            }
            float mx = fmaxf(fmaxf(sv[0], sv[1]), fmaxf(sv[2], sv[3]));
#pragma unroll
            for (int off = 8; off > 0; off >>= 1)
                mx = fmaxf(mx, __shfl_xor_sync(0xffffffffu, mx, off));
            float mnew = fmaxf(m_i[i], mx);
            float corr = __expf(m_i[i] - mnew);
            float p0 = __expf(sv[0] - mnew), p1 = __expf(sv[1] - mnew);
            float p2 = __expf(sv[2] - mnew), p3 = __expf(sv[3] - mnew);
            float sum = p0 + p1 + p2 + p3;
#pragma unroll
            for (int off = 8; off > 0; off >>= 1)
                sum += __shfl_xor_sync(0xffffffffu, sum, off);
            l_i[i] = l_i[i] * corr + sum;
            m_i[i] = mnew;
#pragma unroll
            for (int j = 0; j < 4; j++) o[i][j] *= corr;
            *(float4*)&Ps[(ty*4 + i)*68 + tx*4] = make_float4(p0, p1, p2, p3);
        }
        __syncthreads();
#pragma unroll 16
        for (int k = 0; k < 64; k++) {
            float4 v4 = *(const float4*)&Vs[k*68 + tx*4];
            float pa0 = Ps[(ty*4 + 0)*68 + k];
            float pa1 = Ps[(ty*4 + 1)*68 + k];
            float pa2 = Ps[(ty*4 + 2)*68 + k];
            float pa3 = Ps[(ty*4 + 3)*68 + k];
            o[0][0] += pa0*v4.x; o[0][1] += pa0*v4.y; o[0][2] += pa0*v4.z; o[0][3] += pa0*v4.w;
            o[1][0] += pa1*v4.x; o[1][1] += pa1*v4.y; o[1][2] += pa1*v4.z; o[1][3] += pa1*v4.w;
            o[2][0] += pa2*v4.x; o[2][1] += pa2*v4.y; o[2][2] += pa2*v4.z; o[2][3] += pa2*v4.w;
            o[3][0] += pa3*v4.x; o[3][1] += pa3*v4.y; o[3][2] += pa3*v4.z; o[3][3] += pa3*v4.w;
        }
        __syncthreads();
    }
#pragma unroll
    for (int i = 0; i < 4; i++) {
        float inv = 1.0f / l_i[i];
        float4 w = make_float4(o[i][0]*inv, o[i][1]*inv, o[i][2]*inv, o[i][3]*inv);
        *(float4*)&g_AO[(bh*1024 + q0 + ty*4 + i)*64 + tx*4] = w;
    }
}

// ---------------- GEMM2: out = AO(hidden) @ w_out + b  (4096x1024x1024) ----------------
// A read in native AO [bh][s][d] via summation index r = h*64+d; W rows permuted:
// r -> w_out row (r%64)*16 + r/64
__global__ __launch_bounds__(256, 2)
void k_gemm_out(const float* __restrict__ W, const float* __restrict__ bias,
                float* __restrict__ C) {
    const int N = 1024;
    __shared__ float As[16][132];
    __shared__ float Bs[16][128];
    int t = threadIdx.x, tx = t & 15, ty = t >> 4;
    int m0 = blockIdx.y * 128, n0 = blockIdx.x * 128;
    float acc[8][8];
#pragma unroll
    for (int i = 0; i < 8; i++)
#pragma unroll
        for (int j = 0; j < 8; j++) acc[i][j] = 0.f;
    int ar = t >> 2, ac = (t & 3) << 2;
    int br = t >> 5, bc = (t & 31) << 2;
    int m1 = m0 + ar;
    int ba = m1 >> 10, sa = m1 & 1023;
    for (int k0 = 0; k0 < 1024; k0 += 16) {
        int h = k0 >> 6;
        int dbase = (k0 & 63) + ac;
        const float* ap = g_AO + ((ba*16 + h)*1024 + sa)*64 + dbase;
        float4 a0 = *(const float4*)ap;
        float4 a1 = *(const float4*)(ap + 64*64);   // s + 64
        As[ac+0][ar]    = a0.x; As[ac+1][ar]    = a0.y; As[ac+2][ar]    = a0.z; As[ac+3][ar]    = a0.w;
        As[ac+0][ar+64] = a1.x; As[ac+1][ar+64] = a1.y; As[ac+2][ar+64] = a1.z; As[ac+3][ar+64] = a1.w;
        int r0 = k0 + br, r1 = k0 + br + 8;
        int wr0 = ((r0 & 63) << 4) + (r0 >> 6);
        int wr1 = ((r1 & 63) << 4) + (r1 >> 6);
        *(float4*)&Bs[br  ][bc] = *(const float4*)&W[wr0*N + n0 + bc];
        *(float4*)&Bs[br+8][bc] = *(const float4*)&W[wr1*N + n0 + bc];
        __syncthreads();
#pragma unroll
        for (int kk = 0; kk < 16; kk++) {
            float a[8], bb[8];
            *(float4*)&a[0]  = *(const float4*)&As[kk][ty*8];
            *(float4*)&a[4]  = *(const float4*)&As[kk][ty*8+4];
            *(float4*)&bb[0] = *(const float4*)&Bs[kk][tx*8];
            *(float4*)&bb[4] = *(const float4*)&Bs[kk][tx*8+4];
#pragma unroll
            for (int i = 0; i < 8; i++)
#pragma unroll
                for (int j = 0; j < 8; j++) acc[i][j] += a[i] * bb[j];
        }
        __syncthreads();
    }
#pragma unroll
    for (int i = 0; i < 8; i++) {
        float* cp = C + (m0 + ty*8 + i) * N + n0 + tx*8;
        const float* bp = bias + n0 + tx*8;
        float4 v0, v1;
        v0.x = acc[i][0]+bp[0]; v0.y = acc[i][1]+bp[1]; v0.z = acc[i][2]+bp[2]; v0.w = acc[i][3]+bp[3];
        v1.x = acc[i][4]+bp[4]; v1.y = acc[i][5]+bp[5]; v1.z = acc[i][6]+bp[6]; v1.w = acc[i][7]+bp[7];
        *(float4*)cp = v0; *(float4*)(cp + 4) = v1;
    }
}

extern "C" void kernel_launch(void* const* d_in, const int* in_sizes, int n_in,
                              void* d_out, int out_size) {
    const float* x     = (const float*)d_in[0];
    const int*   mask  = (const int*)  d_in[1];
    const float* w_qkv = (const float*)d_in[2];
    const float* b_qkv = (const float*)d_in[3];
    const float* rel   = (const float*)d_in[4];
    const float* w_out = (const float*)d_in[5];
    const float* b_out = (const float*)d_in[6];
    float* out = (float*)d_out;

    const int relSmem  = (64*68 + 64*260) * 4;     // 83968 B
    const int attnSmem = (4*64*68 + 64*256) * 4;   // 135168 B
    static int configured = 0;
    if (!configured) {
        cudaFuncSetAttribute(k_gemm_rel, cudaFuncAttributeMaxDynamicSharedMemorySize, relSmem);
        cudaFuncSetAttribute(k_attn,     cudaFuncAttributeMaxDynamicSharedMemorySize, attnSmem);
        configured = 1;
    }

    k_gemm_qkv<<<dim3(24, 32), 256>>>(x, w_qkv, b_qkv);
    k_repack  <<<dim3(48, 16, 4), 256>>>();
    k_gemm_rel<<<1024, 256, relSmem>>>(rel);
    k_attn    <<<dim3(16, 64), 256, attnSmem>>>(mask);
    k_gemm_out<<<dim3(8, 32), 256>>>(w_out, b_out, out);
}

// round 9
// speedup vs baseline: 1.0771x; 1.0771x over previous
#include <cuda_runtime.h>
#include <math.h>

#define NB 4
#define NS 1024
#define NH 16
#define HD 64
#define BH (NB*NH)
#define N3 3072

// scratch (static device arrays; no runtime allocation) — R2 set exactly
__device__ float g_qkv[NB*NS*N3];     // [4096][3072]
__device__ float g_Q[BH*HD*NS];       // [bh][d][s]
__device__ float g_K[BH*HD*NS];       // [bh][d][s]
__device__ float g_V[BH*NS*HD];       // [bh][s][d]
__device__ float g_R[BH*NS*256];      // [(bh*1024+q)][256]
__device__ float g_AO[BH*NS*HD];      // [bh][s][d]

// ---------------- GEMM1: qkv = x @ w_qkv + b  (4096x3072x1024) ----------------
__global__ __launch_bounds__(256, 2)
void k_gemm_qkv(const float* __restrict__ X, const float* __restrict__ W,
                const float* __restrict__ bias) {
    const int K = 1024, N = N3;
    __shared__ float As[16][132];
    __shared__ float Bs[16][128];
    int t = threadIdx.x, tx = t & 15, ty = t >> 4;
    int m0 = blockIdx.y * 128, n0 = blockIdx.x * 128;
    float acc[8][8];
#pragma unroll
    for (int i = 0; i < 8; i++)
#pragma unroll
        for (int j = 0; j < 8; j++) acc[i][j] = 0.f;
    int ar = t >> 2, ac = (t & 3) << 2;
    int br = t >> 5, bc = (t & 31) << 2;
    const float* Xp = X + (m0 + ar) * K + ac;
    const float* Wp = W + br * N + n0 + bc;
    for (int k0 = 0; k0 < K; k0 += 16) {
        float4 a0 = *(const float4*)(Xp + k0);
        float4 a1 = *(const float4*)(Xp + 64 * K + k0);
        As[ac+0][ar]    = a0.x; As[ac+1][ar]    = a0.y; As[ac+2][ar]    = a0.z; As[ac+3][ar]    = a0.w;
        As[ac+0][ar+64] = a1.x; As[ac+1][ar+64] = a1.y; As[ac+2][ar+64] = a1.z; As[ac+3][ar+64] = a1.w;
        *(float4*)&Bs[br  ][bc] = *(const float4*)(Wp + k0 * N);
        *(float4*)&Bs[br+8][bc] = *(const float4*)(Wp + (k0 + 8) * N);
        __syncthreads();
#pragma unroll
        for (int kk = 0; kk < 16; kk++) {
            float a[8], b[8];
            *(float4*)&a[0] = *(const float4*)&As[kk][ty*8];
            *(float4*)&a[4] = *(const float4*)&As[kk][ty*8+4];
            *(float4*)&b[0] = *(const float4*)&Bs[kk][tx*8];
            *(float4*)&b[4] = *(const float4*)&Bs[kk][tx*8+4];
#pragma unroll
            for (int i = 0; i < 8; i++)
#pragma unroll
                for (int j = 0; j < 8; j++) acc[i][j] += a[i] * b[j];
        }
        __syncthreads();
    }
#pragma unroll
    for (int i = 0; i < 8; i++) {
        float* cp = g_qkv + (m0 + ty*8 + i) * N + n0 + tx*8;
        const float* bp = bias + n0 + tx*8;
        float4 v0, v1;
        v0.x = acc[i][0]+bp[0]; v0.y = acc[i][1]+bp[1]; v0.z = acc[i][2]+bp[2]; v0.w = acc[i][3]+bp[3];
        v1.x = acc[i][4]+bp[4]; v1.y = acc[i][5]+bp[5]; v1.z = acc[i][6]+bp[6]; v1.w = acc[i][7]+bp[7];
        *(float4*)cp = v0; *(float4*)(cp + 4) = v1;
    }
}

// ---------------- repack qkv -> Q[bh][d][s], K[bh][d][s], V[bh][s][d] ----------------
__global__ __launch_bounds__(256)
void k_repack() {
    __shared__ float smem[64][68];
    int t = threadIdx.x;
    int c0 = blockIdx.x * 64, s0 = blockIdx.y * 64, b = blockIdx.z;
#pragma unroll
    for (int p = 0; p < 4; p++) {
        int lin = t + p * 256;
        int s = lin >> 4, c4 = (lin & 15) << 2;
        *(float4*)&smem[s][c4] = *(const float4*)&g_qkv[(b*1024 + s0 + s)*N3 + c0 + c4];
    }
    __syncthreads();
    int chunk = c0 >> 10;
    int cw = c0 & 1023;
    int dB = cw >> 4;
    if (chunk < 2) {
        float* out = (chunk == 0) ? g_Q : g_K;
#pragma unroll
        for (int p = 0; p < 16; p++) {
            int w = t + p * 256;
            int cc = w >> 6, ss = w & 63;
            int d = dB + (cc >> 4), h = cc & 15;
            out[((b*16 + h)*64 + d)*1024 + s0 + ss] = smem[ss][cc];
        }
    } else {
#pragma unroll
        for (int p = 0; p < 4; p++) {
            int w = t + p * 256;
            int h = w >> 6, ss = w & 63;
            float4 v;
            v.x = smem[ss][h]; v.y = smem[ss][16+h]; v.z = smem[ss][32+h]; v.w = smem[ss][48+h];
            *(float4*)&g_V[((b*16 + h)*1024 + s0 + ss)*64 + dB] = v;
        }
    }
}

// ---------------- R[bh*1024+s, j] = sum_d Q[bh][d][s] * rel[j][d], j<255 ----------------
__global__ __launch_bounds__(256)
void k_gemm_rel(const float* __restrict__ rel) {
    extern __shared__ float sm[];
    float* As   = sm;              // [d][s] stride 68
    float* RelT = sm + 64*68;      // [d][j] stride 260
    int t = threadIdx.x, tx = t & 31, ty = t >> 5;
    int mt = blockIdx.x;
    int bh = mt >> 4, s0 = (mt & 15) << 6;
#pragma unroll
    for (int p = 0; p < 4; p++) {
        int lin = t + p * 256;
        int d = lin >> 4, c4 = (lin & 15) << 2;
        *(float4*)&As[d*68 + c4] = *(const float4*)&g_Q[(bh*64 + d)*1024 + s0 + c4];
    }
    for (int e = t; e < 255*64; e += 256) {
        int j = e >> 6, d = e & 63;
        RelT[d*260 + j] = rel[e];
    }
    if (t < 64) RelT[t*260 + 255] = 0.f;
    __syncthreads();
    float acc[8][8];
#pragma unroll
    for (int i = 0; i < 8; i++)
#pragma unroll
        for (int j = 0; j < 8; j++) acc[i][j] = 0.f;
#pragma unroll 16
    for (int d = 0; d < 64; d++) {
        float a[8], bb[8];
        *(float4*)&a[0]  = *(const float4*)&As[d*68 + ty*8];
        *(float4*)&a[4]  = *(const float4*)&As[d*68 + ty*8 + 4];
        *(float4*)&bb[0] = *(const float4*)&RelT[d*260 + tx*8];
        *(float4*)&bb[4] = *(const float4*)&RelT[d*260 + tx*8 + 4];
#pragma unroll
        for (int i = 0; i < 8; i++)
#pragma unroll
            for (int j = 0; j < 8; j++) acc[i][j] += a[i] * bb[j];
    }
#pragma unroll
    for (int i = 0; i < 8; i++) {
        float* rp = g_R + (mt*64 + ty*8 + i)*256 + tx*8;
        *(float4*)rp       = make_float4(acc[i][0], acc[i][1], acc[i][2], acc[i][3]);
        *(float4*)(rp + 4) = make_float4(acc[i][4], acc[i][5], acc[i][6], acc[i][7]);
    }
}

// ---------------- flash attention: stride 64 + KsT/Ps aliased -> smem 114688 (2 CTAs/SM) ----------------
__global__ __launch_bounds__(256, 1)
void k_attn(const int* __restrict__ mask) {
    extern __shared__ float sm[];
    float* QsT = sm;               // [d][q]  stride 64
    float* KP  = sm + 4096;        // KsT during QK phase; Ps during PV phase (aliased)
    float* Vs  = sm + 8192;        // [k][d]  stride 64
    float* Rs  = sm + 12288;       // [q][256]
    int t = threadIdx.x, tx = t & 15, ty = t >> 4;
    int qt = blockIdx.x, bh = blockIdx.y;
    int b = bh >> 4, q0 = qt << 6;
#pragma unroll
    for (int p = 0; p < 4; p++) {
        int lin = t + p * 256;
        int d = lin >> 4, c4 = (lin & 15) << 2;
        *(float4*)&QsT[d*64 + c4] = *(const float4*)&g_Q[(bh*64 + d)*1024 + q0 + c4];
    }
#pragma unroll
    for (int p = 0; p < 16; p++) {
        int lin = t + p * 256;
        int q = lin >> 6, j4 = (lin & 63) << 2;
        *(float4*)&Rs[q*256 + j4] = *(const float4*)&g_R[(bh*1024 + q0 + q)*256 + j4];
    }
    float m_i[4], l_i[4], o[4][4];
#pragma unroll
    for (int i = 0; i < 4; i++) {
        m_i[i] = -INFINITY; l_i[i] = 0.f;
#pragma unroll
        for (int j = 0; j < 4; j++) o[i][j] = 0.f;
    }
    __syncthreads();
    for (int kt = 0; kt < 16; kt++) {
#pragma unroll
        for (int p = 0; p < 4; p++) {
            int lin = t + p * 256;
            int r = lin >> 4, c4 = (lin & 15) << 2;
            *(float4*)&KP[r*64 + c4] = *(const float4*)&g_K[(bh*64 + r)*1024 + kt*64 + c4];
            *(float4*)&Vs[r*64 + c4] = *(const float4*)&g_V[(bh*1024 + kt*64 + r)*64 + c4];
        }
        __syncthreads();
        float s4[4][4];
#pragma unroll
        for (int i = 0; i < 4; i++)
#pragma unroll
            for (int j = 0; j < 4; j++) s4[i][j] = 0.f;
#pragma unroll 16
        for (int d = 0; d < 64; d++) {
            float4 aq = *(const float4*)&QsT[d*64 + ty*4];
            float4 bk = *(const float4*)&KP[d*64 + tx*4];
            s4[0][0] += aq.x*bk.x; s4[0][1] += aq.x*bk.y; s4[0][2] += aq.x*bk.z; s4[0][3] += aq.x*bk.w;
            s4[1][0] += aq.y*bk.x; s4[1][1] += aq.y*bk.y; s4[1][2] += aq.y*bk.z; s4[1][3] += aq.y*bk.w;
            s4[2][0] += aq.z*bk.x; s4[2][1] += aq.z*bk.y; s4[2][2] += aq.z*bk.z; s4[2][3] += aq.z*bk.w;
            s4[3][0] += aq.w*bk.x; s4[3][1] += aq.w*bk.y; s4[3][2] += aq.w*bk.z; s4[3][3] += aq.w*bk.w;
        }
        __syncthreads();   // all QK reads of KP complete before Ps overwrites it
        int kg0 = kt*64 + tx*4;
#pragma unroll
        for (int i = 0; i < 4; i++) {
            int qg = q0 + ty*4 + i;
            int4 mv = *(const int4*)&mask[(b*1024 + qg)*1024 + kg0];
            int mm[4] = {mv.x, mv.y, mv.z, mv.w};
            float sv[4];
#pragma unroll
            for (int j = 0; j < 4; j++) {
                int r = kg0 + j - qg;
                r = min(127, max(-127, r));
                float v = 8.0f * s4[i][j] + Rs[(ty*4 + i)*256 + r + 127];
                sv[j] = (mm[j] == 0) ? -1e8f : v;
            }
            float mx = fmaxf(fmaxf(sv[0], sv[1]), fmaxf(sv[2], sv[3]));
#pragma unroll
            for (int off = 8; off > 0; off >>= 1)
                mx = fmaxf(mx, __shfl_xor_sync(0xffffffffu, mx, off));
            float mnew = fmaxf(m_i[i], mx);
            float corr = __expf(m_i[i] - mnew);
            float p0 = __expf(sv[0] - mnew), p1 = __expf(sv[1] - mnew);
            float p2 = __expf(sv[2] - mnew), p3 = __expf(sv[3] - mnew);
            float sum = p0 + p1 + p2 + p3;
#pragma unroll
            for (int off = 8; off > 0; off >>= 1)
                sum += __shfl_xor_sync(0xffffffffu, sum, off);
            l_i[i] = l_i[i] * corr + sum;
            m_i[i] = mnew;
#pragma unroll
            for (int j = 0; j < 4; j++) o[i][j] *= corr;
            *(float4*)&KP[(ty*4 + i)*64 + tx*4] = make_float4(p0, p1, p2, p3);   // Ps
        }
        __syncthreads();
#pragma unroll 16
        for (int k = 0; k < 64; k++) {
            float4 v4 = *(const float4*)&Vs[k*64 + tx*4];
            float pa0 = KP[(ty*4 + 0)*64 + k];
            float pa1 = KP[(ty*4 + 1)*64 + k];
            float pa2 = KP[(ty*4 + 2)*64 + k];
            float pa3 = KP[(ty*4 + 3)*64 + k];
            o[0][0] += pa0*v4.x; o[0][1] += pa0*v4.y; o[0][2] += pa0*v4.z; o[0][3] += pa0*v4.w;
            o[1][0] += pa1*v4.x; o[1][1] += pa1*v4.y; o[1][2] += pa1*v4.z; o[1][3] += pa1*v4.w;
            o[2][0] += pa2*v4.x; o[2][1] += pa2*v4.y; o[2][2] += pa2*v4.z; o[2][3] += pa2*v4.w;
            o[3][0] += pa3*v4.x; o[3][1] += pa3*v4.y; o[3][2] += pa3*v4.z; o[3][3] += pa3*v4.w;
        }
        __syncthreads();
    }
#pragma unroll
    for (int i = 0; i < 4; i++) {
        float inv = 1.0f / l_i[i];
        float4 w = make_float4(o[i][0]*inv, o[i][1]*inv, o[i][2]*inv, o[i][3]*inv);
        *(float4*)&g_AO[(bh*1024 + q0 + ty*4 + i)*64 + tx*4] = w;
    }
}

// ---------------- GEMM2: out = AO(hidden) @ w_out + b  (4096x1024x1024) ----------------
__global__ __launch_bounds__(256, 2)
void k_gemm_out(const float* __restrict__ W, const float* __restrict__ bias,
                float* __restrict__ C) {
    const int N = 1024;
    __shared__ float As[16][132];
    __shared__ float Bs[16][128];
    int t = threadIdx.x, tx = t & 15, ty = t >> 4;
    int m0 = blockIdx.y * 128, n0 = blockIdx.x * 128;
    float acc[8][8];
#pragma unroll
    for (int i = 0; i < 8; i++)
#pragma unroll
        for (int j = 0; j < 8; j++) acc[i][j] = 0.f;
    int ar = t >> 2, ac = (t & 3) << 2;
    int br = t >> 5, bc = (t & 31) << 2;
    int m1 = m0 + ar;
    int ba = m1 >> 10, sa = m1 & 1023;
    for (int k0 = 0; k0 < 1024; k0 += 16) {
        int h = k0 >> 6;
        int dbase = (k0 & 63) + ac;
        const float* ap = g_AO + ((ba*16 + h)*1024 + sa)*64 + dbase;
        float4 a0 = *(const float4*)ap;
        float4 a1 = *(const float4*)(ap + 64*64);   // s + 64
        As[ac+0][ar]    = a0.x; As[ac+1][ar]    = a0.y; As[ac+2][ar]    = a0.z; As[ac+3][ar]    = a0.w;
        As[ac+0][ar+64] = a1.x; As[ac+1][ar+64] = a1.y; As[ac+2][ar+64] = a1.z; As[ac+3][ar+64] = a1.w;
        int r0 = k0 + br, r1 = k0 + br + 8;
        int wr0 = ((r0 & 63) << 4) + (r0 >> 6);
        int wr1 = ((r1 & 63) << 4) + (r1 >> 6);
        *(float4*)&Bs[br  ][bc] = *(const float4*)&W[wr0*N + n0 + bc];
        *(float4*)&Bs[br+8][bc] = *(const float4*)&W[wr1*N + n0 + bc];
        __syncthreads();
#pragma unroll
        for (int kk = 0; kk < 16; kk++) {
            float a[8], bb[8];
            *(float4*)&a[0]  = *(const float4*)&As[kk][ty*8];
            *(float4*)&a[4]  = *(const float4*)&As[kk][ty*8+4];
            *(float4*)&bb[0] = *(const float4*)&Bs[kk][tx*8];
            *(float4*)&bb[4] = *(const float4*)&Bs[kk][tx*8+4];
#pragma unroll
            for (int i = 0; i < 8; i++)
#pragma unroll
                for (int j = 0; j < 8; j++) acc[i][j] += a[i] * bb[j];
        }
        __syncthreads();
    }
#pragma unroll
    for (int i = 0; i < 8; i++) {
        float* cp = C + (m0 + ty*8 + i) * N + n0 + tx*8;
        const float* bp = bias + n0 + tx*8;
        float4 v0, v1;
        v0.x = acc[i][0]+bp[0]; v0.y = acc[i][1]+bp[1]; v0.z = acc[i][2]+bp[2]; v0.w = acc[i][3]+bp[3];
        v1.x = acc[i][4]+bp[4]; v1.y = acc[i][5]+bp[5]; v1.z = acc[i][6]+bp[6]; v1.w = acc[i][7]+bp[7];
        *(float4*)cp = v0; *(float4*)(cp + 4) = v1;
    }
}

extern "C" void kernel_launch(void* const* d_in, const int* in_sizes, int n_in,
                              void* d_out, int out_size) {
    const float* x     = (const float*)d_in[0];
    const int*   mask  = (const int*)  d_in[1];
    const float* w_qkv = (const float*)d_in[2];
    const float* b_qkv = (const float*)d_in[3];
    const float* rel   = (const float*)d_in[4];
    const float* w_out = (const float*)d_in[5];
    const float* b_out = (const float*)d_in[6];
    float* out = (float*)d_out;

    const int relSmem  = (64*68 + 64*260) * 4;     // 83968
    const int attnSmem = (3*64*64 + 64*256) * 4;   // 114688
    static int configured = 0;
    if (!configured) {
        cudaFuncSetAttribute(k_gemm_rel, cudaFuncAttributeMaxDynamicSharedMemorySize, relSmem);
        cudaFuncSetAttribute(k_attn,     cudaFuncAttributeMaxDynamicSharedMemorySize, attnSmem);
        configured = 1;
    }

    k_gemm_qkv<<<dim3(24, 32), 256>>>(x, w_qkv, b_qkv);
    k_repack  <<<dim3(48, 16, 4), 256>>>();
    k_gemm_rel<<<1024, 256, relSmem>>>(rel);
    k_attn    <<<dim3(16, 64), 256, attnSmem>>>(mask);
    k_gemm_out<<<dim3(8, 32), 256>>>(w_out, b_out, out);
}

// round 10
// speedup vs baseline: 1.2018x; 1.1158x over previous
#include <cuda_runtime.h>
#include <cuda_bf16.h>
#include <math.h>
#include <stdint.h>

#define NB 4
#define NS 1024
#define NH 16
#define HD 64
#define BH (NB*NH)
#define N3 3072

// scratch — identical static set to passing R9
__device__ float g_qkv[NB*NS*N3];     // [4096][3072]
__device__ float g_Q[BH*HD*NS];       // [bh][d][s]
__device__ float g_K[BH*HD*NS];       // [bh][d][s]
__device__ float g_V[BH*NS*HD];       // [bh][s][d]
__device__ float g_R[BH*NS*256];      // [(bh*1024+q)][256]
__device__ float g_AO[BH*NS*HD];      // [bh][s][d]

// ---------------- split helpers (registers only) ----------------
__device__ __forceinline__ uint32_t pack2bf(float a, float b) {
    __nv_bfloat162 t = __floats2bfloat162_rn(a, b);
    return *reinterpret_cast<uint32_t*>(&t);
}
__device__ __forceinline__ float bf_res(float a) {
    return a - __bfloat162float(__float2bfloat16(a));
}

// ---------------- GEMM1 via split-bf16 mma.sync ----------------
// C[4096][3072] = X[4096][1024] @ W[1024][3072] + bias
// block 128m x 64n, 8 warps (4m x 2n), warp 32x32; K-slab 32; 3-term split.
#define SMS 40

#define MMA_OP(D, A, B0, B1)                                            \
    asm volatile(                                                       \
        "mma.sync.aligned.m16n8k16.row.col.f32.bf16.bf16.f32 "          \
        "{%0,%1,%2,%3}, {%4,%5,%6,%7}, {%8,%9}, {%0,%1,%2,%3};"         \
        : "+f"(D.x), "+f"(D.y), "+f"(D.z), "+f"(D.w)                    \
        : "r"(A.x), "r"(A.y), "r"(A.z), "r"(A.w), "r"(B0), "r"(B1))

#define LD32S(arr, idx) (*(const uint32_t*)&(arr)[idx])

#define NTSTEP(CA, CB, NT) {                                            \
    int rb_ = (wn*32 + (NT)*8 + g)*SMS + cc;                            \
    uint32_t b0h_ = LD32S(sBh, rb_), b1h_ = LD32S(sBh, rb_ + 8);        \
    uint32_t b0l_ = LD32S(sBl, rb_), b1l_ = LD32S(sBl, rb_ + 8);        \
    MMA_OP(CA, a0h, b0h_, b1h_); MMA_OP(CA, a0h, b0l_, b1l_);           \
    MMA_OP(CA, a0l, b0h_, b1h_);                                        \
    MMA_OP(CB, a1h, b0h_, b1h_); MMA_OP(CB, a1h, b0l_, b1l_);           \
    MMA_OP(CB, a1l, b0h_, b1h_); }

#define KSTEP(KK) {                                                     \
    const int cc = (KK) + tq*2;                                         \
    uint4 a0h, a1h, a0l, a1l;                                           \
    {   int ra_ = (wm*32 + g)*SMS + cc;                                 \
        a0h.x = LD32S(sAh, ra_);            a0h.y = LD32S(sAh, ra_ + 8*SMS); \
        a0h.z = LD32S(sAh, ra_ + 8);        a0h.w = LD32S(sAh, ra_ + 8*SMS + 8); \
        a0l.x = LD32S(sAl, ra_);            a0l.y = LD32S(sAl, ra_ + 8*SMS); \
        a0l.z = LD32S(sAl, ra_ + 8);        a0l.w = LD32S(sAl, ra_ + 8*SMS + 8); \
        int rb_ = ra_ + 16*SMS;                                         \
        a1h.x = LD32S(sAh, rb_);            a1h.y = LD32S(sAh, rb_ + 8*SMS); \
        a1h.z = LD32S(sAh, rb_ + 8);        a1h.w = LD32S(sAh, rb_ + 8*SMS + 8); \
        a1l.x = LD32S(sAl, rb_);            a1l.y = LD32S(sAl, rb_ + 8*SMS); \
        a1l.z = LD32S(sAl, rb_ + 8);        a1l.w = LD32S(sAl, rb_ + 8*SMS + 8); } \
    NTSTEP(c00, c10, 0); NTSTEP(c01, c11, 1);                           \
    NTSTEP(c02, c12, 2); NTSTEP(c03, c13, 3); }

#define STORE1(CMN, MT, NT) {                                           \
    int r_ = m0 + wm*32 + (MT)*16 + g;                                  \
    int c_ = n0 + wn*32 + (NT)*8 + tq*2;                                \
    float b0_ = bias[c_], b1_ = bias[c_+1];                             \
    *(float2*)&C[(size_t)r_ * N + c_] = make_float2(CMN.x + b0_, CMN.y + b1_); \
    *(float2*)&C[(size_t)(r_+8) * N + c_] = make_float2(CMN.z + b0_, CMN.w + b1_); }

__global__ __launch_bounds__(256)
void k_gemm1_mma(const float* __restrict__ X, const float* __restrict__ W,
                 const float* __restrict__ bias) {
    const int N = N3, K = 1024;
    __shared__ __align__(16) __nv_bfloat16 sAh[128*SMS], sAl[128*SMS];
    __shared__ __align__(16) __nv_bfloat16 sBh[64*SMS],  sBl[64*SMS];
    float* C = g_qkv;
    int t = threadIdx.x, lane = t & 31, warp = t >> 5;
    int wm = warp >> 1, wn = warp & 1;
    int g = lane >> 2, tq = lane & 3;
    int m0 = blockIdx.y * 128, n0 = blockIdx.x * 64;
    float4 c00 = make_float4(0.f,0.f,0.f,0.f), c01 = c00, c02 = c00, c03 = c00;
    float4 c10 = c00, c11 = c00, c12 = c00, c13 = c00;

    for (int k0 = 0; k0 < K; k0 += 32) {
        // A: 128 rows x 32 k, fp32 -> hi/lo bf16 inline
#pragma unroll
        for (int p = 0; p < 4; p++) {
            int idx = t + p * 256;
            int row = idx >> 3, k4 = (idx & 7) << 2;
            float4 v = *(const float4*)&X[(size_t)(m0 + row) * K + k0 + k4];
            int so = row*SMS + k4;
            *(uint32_t*)&sAh[so]     = pack2bf(v.x, v.y);
            *(uint32_t*)&sAh[so + 2] = pack2bf(v.z, v.w);
            *(uint32_t*)&sAl[so]     = pack2bf(bf_res(v.x), bf_res(v.y));
            *(uint32_t*)&sAl[so + 2] = pack2bf(bf_res(v.z), bf_res(v.w));
        }
        // B: W[k][n] tile 32k x 64n -> transposed smem [n][k], hi/lo inline
#pragma unroll
        for (int p = 0; p < 2; p++) {
            int idx = t + p * 256;
            int kr = idx >> 4, n4 = (idx & 15) << 2;
            float4 w = *(const float4*)&W[(size_t)(k0 + kr) * N + n0 + n4];
            sBh[(n4+0)*SMS + kr] = __float2bfloat16(w.x);
            sBh[(n4+1)*SMS + kr] = __float2bfloat16(w.y);
            sBh[(n4+2)*SMS + kr] = __float2bfloat16(w.z);
            sBh[(n4+3)*SMS + kr] = __float2bfloat16(w.w);
            sBl[(n4+0)*SMS + kr] = __float2bfloat16(bf_res(w.x));
            sBl[(n4+1)*SMS + kr] = __float2bfloat16(bf_res(w.y));
            sBl[(n4+2)*SMS + kr] = __float2bfloat16(bf_res(w.z));
            sBl[(n4+3)*SMS + kr] = __float2bfloat16(bf_res(w.w));
        }
        __syncthreads();
        KSTEP(0);
        KSTEP(16);
        __syncthreads();
    }
    STORE1(c00, 0, 0); STORE1(c01, 0, 1); STORE1(c02, 0, 2); STORE1(c03, 0, 3);
    STORE1(c10, 1, 0); STORE1(c11, 1, 1); STORE1(c12, 1, 2); STORE1(c13, 1, 3);
}

// ---------------- repack qkv -> Q[bh][d][s], K[bh][d][s], V[bh][s][d] (R9) ----------------
__global__ __launch_bounds__(256)
void k_repack() {
    __shared__ float smem[64][68];
    int t = threadIdx.x;
    int c0 = blockIdx.x * 64, s0 = blockIdx.y * 64, b = blockIdx.z;
#pragma unroll
    for (int p = 0; p < 4; p++) {
        int lin = t + p * 256;
        int s = lin >> 4, c4 = (lin & 15) << 2;
        *(float4*)&smem[s][c4] = *(const float4*)&g_qkv[(b*1024 + s0 + s)*N3 + c0 + c4];
    }
    __syncthreads();
    int chunk = c0 >> 10;
    int cw = c0 & 1023;
    int dB = cw >> 4;
    if (chunk < 2) {
        float* out = (chunk == 0) ? g_Q : g_K;
#pragma unroll
        for (int p = 0; p < 16; p++) {
            int w = t + p * 256;
            int cc = w >> 6, ss = w & 63;
            int d = dB + (cc >> 4), h = cc & 15;
            out[((b*16 + h)*64 + d)*1024 + s0 + ss] = smem[ss][cc];
        }
    } else {
#pragma unroll
        for (int p = 0; p < 4; p++) {
            int w = t + p * 256;
            int h = w >> 6, ss = w & 63;
            float4 v;
            v.x = smem[ss][h]; v.y = smem[ss][16+h]; v.z = smem[ss][32+h]; v.w = smem[ss][48+h];
            *(float4*)&g_V[((b*16 + h)*1024 + s0 + ss)*64 + dB] = v;
        }
    }
}

// ---------------- R = Q . rel^T (R9) ----------------
__global__ __launch_bounds__(256)
void k_gemm_rel(const float* __restrict__ rel) {
    extern __shared__ float sm[];
    float* As   = sm;              // [d][s] s68
    float* RelT = sm + 64*68;      // [d][j] s260
    int t = threadIdx.x, tx = t & 31, ty = t >> 5;
    int mt = blockIdx.x;
    int bh = mt >> 4, s0 = (mt & 15) << 6;
#pragma unroll
    for (int p = 0; p < 4; p++) {
        int lin = t + p * 256;
        int d = lin >> 4, c4 = (lin & 15) << 2;
        *(float4*)&As[d*68 + c4] = *(const float4*)&g_Q[(bh*64 + d)*1024 + s0 + c4];
    }
    for (int e = t; e < 255*64; e += 256) {
        int j = e >> 6, d = e & 63;
        RelT[d*260 + j] = rel[e];
    }
    if (t < 64) RelT[t*260 + 255] = 0.f;
    __syncthreads();
    float acc[8][8];
#pragma unroll
    for (int i = 0; i < 8; i++)
#pragma unroll
        for (int j = 0; j < 8; j++) acc[i][j] = 0.f;
#pragma unroll 16
    for (int d = 0; d < 64; d++) {
        float a[8], bb[8];
        *(float4*)&a[0]  = *(const float4*)&As[d*68 + ty*8];
        *(float4*)&a[4]  = *(const float4*)&As[d*68 + ty*8 + 4];
        *(float4*)&bb[0] = *(const float4*)&RelT[d*260 + tx*8];
        *(float4*)&bb[4] = *(const float4*)&RelT[d*260 + tx*8 + 4];
#pragma unroll
        for (int i = 0; i < 8; i++)
#pragma unroll
            for (int j = 0; j < 8; j++) acc[i][j] += a[i] * bb[j];
    }
#pragma unroll
    for (int i = 0; i < 8; i++) {
        float* rp = g_R + (mt*64 + ty*8 + i)*256 + tx*8;
        *(float4*)rp       = make_float4(acc[i][0], acc[i][1], acc[i][2], acc[i][3]);
        *(float4*)(rp + 4) = make_float4(acc[i][4], acc[i][5], acc[i][6], acc[i][7]);
    }
}

// ---------------- flash attention (R9: stride 64, KsT/Ps aliased, smem 114688) ----------------
__global__ __launch_bounds__(256, 1)
void k_attn(const int* __restrict__ mask) {
    extern __shared__ float sm[];
    float* QsT = sm;               // [d][q] s64
    float* KP  = sm + 4096;        // KsT / Ps aliased
    float* Vs  = sm + 8192;        // [k][d] s64
    float* Rs  = sm + 12288;       // [q][256]
    int t = threadIdx.x, tx = t & 15, ty = t >> 4;
    int qt = blockIdx.x, bh = blockIdx.y;
    int b = bh >> 4, q0 = qt << 6;
#pragma unroll
    for (int p = 0; p < 4; p++) {
        int lin = t + p * 256;
        int d = lin >> 4, c4 = (lin & 15) << 2;
        *(float4*)&QsT[d*64 + c4] = *(const float4*)&g_Q[(bh*64 + d)*1024 + q0 + c4];
    }
#pragma unroll
    for (int p = 0; p < 16; p++) {
        int lin = t + p * 256;
        int q = lin >> 6, j4 = (lin & 63) << 2;
        *(float4*)&Rs[q*256 + j4] = *(const float4*)&g_R[(bh*1024 + q0 + q)*256 + j4];
    }
    float m_i[4], l_i[4], o[4][4];
#pragma unroll
    for (int i = 0; i < 4; i++) {
        m_i[i] = -INFINITY; l_i[i] = 0.f;
#pragma unroll
        for (int j = 0; j < 4; j++) o[i][j] = 0.f;
    }
    __syncthreads();
    for (int kt = 0; kt < 16; kt++) {
#pragma unroll
        for (int p = 0; p < 4; p++) {
            int lin = t + p * 256;
            int r = lin >> 4, c4 = (lin & 15) << 2;
            *(float4*)&KP[r*64 + c4] = *(const float4*)&g_K[(bh*64 + r)*1024 + kt*64 + c4];
            *(float4*)&Vs[r*64 + c4] = *(const float4*)&g_V[(bh*1024 + kt*64 + r)*64 + c4];
        }
        __syncthreads();
        float s4[4][4];
#pragma unroll
        for (int i = 0; i < 4; i++)
#pragma unroll
            for (int j = 0; j < 4; j++) s4[i][j] = 0.f;
#pragma unroll 16
        for (int d = 0; d < 64; d++) {
            float4 aq = *(const float4*)&QsT[d*64 + ty*4];
            float4 bk = *(const float4*)&KP[d*64 + tx*4];
            s4[0][0] += aq.x*bk.x; s4[0][1] += aq.x*bk.y; s4[0][2] += aq.x*bk.z; s4[0][3] += aq.x*bk.w;
            s4[1][0] += aq.y*bk.x; s4[1][1] += aq.y*bk.y; s4[1][2] += aq.y*bk.z; s4[1][3] += aq.y*bk.w;
            s4[2][0] += aq.z*bk.x; s4[2][1] += aq.z*bk.y; s4[2][2] += aq.z*bk.z; s4[2][3] += aq.z*bk.w;
            s4[3][0] += aq.w*bk.x; s4[3][1] += aq.w*bk.y; s4[3][2] += aq.w*bk.z; s4[3][3] += aq.w*bk.w;
        }
        __syncthreads();
        int kg0 = kt*64 + tx*4;
#pragma unroll
        for (int i = 0; i < 4; i++) {
            int qg = q0 + ty*4 + i;
            int4 mv = *(const int4*)&mask[(b*1024 + qg)*1024 + kg0];
            int mm[4] = {mv.x, mv.y, mv.z, mv.w};
            float sv[4];
#pragma unroll
            for (int j = 0; j < 4; j++) {
                int r = kg0 + j - qg;
                r = min(127, max(-127, r));
                float v = 8.0f * s4[i][j] + Rs[(ty*4 + i)*256 + r + 127];
                sv[j] = (mm[j] == 0) ? -1e8f : v;
            }
            float mx = fmaxf(fmaxf(sv[0], sv[1]), fmaxf(sv[2], sv[3]));
#pragma unroll
            for (int off = 8; off > 0; off >>= 1)
                mx = fmaxf(mx, __shfl_xor_sync(0xffffffffu, mx, off));
            float mnew = fmaxf(m_i[i], mx);
            float corr = __expf(m_i[i] - mnew);
            float p0 = __expf(sv[0] - mnew), p1 = __expf(sv[1] - mnew);
            float p2 = __expf(sv[2] - mnew), p3 = __expf(sv[3] - mnew);
            float sum = p0 + p1 + p2 + p3;
#pragma unroll
            for (int off = 8; off > 0; off >>= 1)
                sum += __shfl_xor_sync(0xffffffffu, sum, off);
            l_i[i] = l_i[i] * corr + sum;
            m_i[i] = mnew;
#pragma unroll
            for (int j = 0; j < 4; j++) o[i][j] *= corr;
            *(float4*)&KP[(ty*4 + i)*64 + tx*4] = make_float4(p0, p1, p2, p3);
        }
        __syncthreads();
#pragma unroll 16
        for (int k = 0; k < 64; k++) {
            float4 v4 = *(const float4*)&Vs[k*64 + tx*4];
            float pa0 = KP[(ty*4 + 0)*64 + k];
            float pa1 = KP[(ty*4 + 1)*64 + k];
            float pa2 = KP[(ty*4 + 2)*64 + k];
            float pa3 = KP[(ty*4 + 3)*64 + k];
            o[0][0] += pa0*v4.x; o[0][1] += pa0*v4.y; o[0][2] += pa0*v4.z; o[0][3] += pa0*v4.w;
            o[1][0] += pa1*v4.x; o[1][1] += pa1*v4.y; o[1][2] += pa1*v4.z; o[1][3] += pa1*v4.w;
            o[2][0] += pa2*v4.x; o[2][1] += pa2*v4.y; o[2][2] += pa2*v4.z; o[2][3] += pa2*v4.w;
            o[3][0] += pa3*v4.x; o[3][1] += pa3*v4.y; o[3][2] += pa3*v4.z; o[3][3] += pa3*v4.w;
        }
        __syncthreads();
    }
#pragma unroll
    for (int i = 0; i < 4; i++) {
        float inv = 1.0f / l_i[i];
        float4 w = make_float4(o[i][0]*inv, o[i][1]*inv, o[i][2]*inv, o[i][3]*inv);
        *(float4*)&g_AO[(bh*1024 + q0 + ty*4 + i)*64 + tx*4] = w;
    }
}

// ---------------- GEMM2: out = AO(hidden) @ w_out + b  (R9 FFMA) ----------------
__global__ __launch_bounds__(256, 2)
void k_gemm_out(const float* __restrict__ W, const float* __restrict__ bias,
                float* __restrict__ C) {
    const int N = 1024;
    __shared__ float As[16][132];
    __shared__ float Bs[16][128];
    int t = threadIdx.x, tx = t & 15, ty = t >> 4;
    int m0 = blockIdx.y * 128, n0 = blockIdx.x * 128;
    float acc[8][8];
#pragma unroll
    for (int i = 0; i < 8; i++)
#pragma unroll
        for (int j = 0; j < 8; j++) acc[i][j] = 0.f;
    int ar = t >> 2, ac = (t & 3) << 2;
    int br = t >> 5, bc = (t & 31) << 2;
    int m1 = m0 + ar;
    int ba = m1 >> 10, sa = m1 & 1023;
    for (int k0 = 0; k0 < 1024; k0 += 16) {
        int h = k0 >> 6;
        int dbase = (k0 & 63) + ac;
        const float* ap = g_AO + ((ba*16 + h)*1024 + sa)*64 + dbase;
        float4 a0 = *(const float4*)ap;
        float4 a1 = *(const float4*)(ap + 64*64);
        As[ac+0][ar]    = a0.x; As[ac+1][ar]    = a0.y; As[ac+2][ar]    = a0.z; As[ac+3][ar]    = a0.w;
        As[ac+0][ar+64] = a1.x; As[ac+1][ar+64] = a1.y; As[ac+2][ar+64] = a1.z; As[ac+3][ar+64] = a1.w;
        int r0 = k0 + br, r1 = k0 + br + 8;
        int wr0 = ((r0 & 63) << 4) + (r0 >> 6);
        int wr1 = ((r1 & 63) << 4) + (r1 >> 6);
        *(float4*)&Bs[br  ][bc] = *(const float4*)&W[wr0*N + n0 + bc];
        *(float4*)&Bs[br+8][bc] = *(const float4*)&W[wr1*N + n0 + bc];
        __syncthreads();
#pragma unroll
        for (int kk = 0; kk < 16; kk++) {
            float a[8], bb[8];
            *(float4*)&a[0]  = *(const float4*)&As[kk][ty*8];
            *(float4*)&a[4]  = *(const float4*)&As[kk][ty*8+4];
            *(float4*)&bb[0] = *(const float4*)&Bs[kk][tx*8];
            *(float4*)&bb[4] = *(const float4*)&Bs[kk][tx*8+4];
#pragma unroll
            for (int i = 0; i < 8; i++)
#pragma unroll
                for (int j = 0; j < 8; j++) acc[i][j] += a[i] * bb[j];
        }
        __syncthreads();
    }
#pragma unroll
    for (int i = 0; i < 8; i++) {
        float* cp = C + (m0 + ty*8 + i) * N + n0 + tx*8;
        const float* bp = bias + n0 + tx*8;
        float4 v0, v1;
        v0.x = acc[i][0]+bp[0]; v0.y = acc[i][1]+bp[1]; v0.z = acc[i][2]+bp[2]; v0.w = acc[i][3]+bp[3];
        v1.x = acc[i][4]+bp[4]; v1.y = acc[i][5]+bp[5]; v1.z = acc[i][6]+bp[6]; v1.w = acc[i][7]+bp[7];
        *(float4*)cp = v0; *(float4*)(cp + 4) = v1;
    }
}

extern "C" void kernel_launch(void* const* d_in, const int* in_sizes, int n_in,
                              void* d_out, int out_size) {
    const float* x     = (const float*)d_in[0];
    const int*   mask  = (const int*)  d_in[1];
    const float* w_qkv = (const float*)d_in[2];
    const float* b_qkv = (const float*)d_in[3];
    const float* rel   = (const float*)d_in[4];
    const float* w_out = (const float*)d_in[5];
    const float* b_out = (const float*)d_in[6];
    float* out = (float*)d_out;

    const int relSmem  = (64*68 + 64*260) * 4;     // 83968
    const int attnSmem = (3*64*64 + 64*256) * 4;   // 114688
    static int configured = 0;
    if (!configured) {
        cudaFuncSetAttribute(k_gemm_rel, cudaFuncAttributeMaxDynamicSharedMemorySize, relSmem);
        cudaFuncSetAttribute(k_attn,     cudaFuncAttributeMaxDynamicSharedMemorySize, attnSmem);
        configured = 1;
    }

    k_gemm1_mma<<<dim3(48, 32), 256>>>(x, w_qkv, b_qkv);
    k_repack   <<<dim3(48, 16, 4), 256>>>();
    k_gemm_rel <<<1024, 256, relSmem>>>(rel);
    k_attn     <<<dim3(16, 64), 256, attnSmem>>>(mask);
    k_gemm_out <<<dim3(8, 32), 256>>>(w_out, b_out, out);
}

// round 12
// speedup vs baseline: 1.2291x; 1.0228x over previous
#include <cuda_runtime.h>
#include <cuda_bf16.h>
#include <math.h>
#include <stdint.h>

#define NB 4
#define NS 1024
#define NH 16
#define HD 64
#define BH (NB*NH)
#define N3 3072

// scratch — identical static set to passing R9/R10
__device__ float g_qkv[NB*NS*N3];     // [4096][3072]
__device__ float g_Q[BH*HD*NS];       // [bh][d][s]
__device__ float g_K[BH*HD*NS];       // [bh][d][s]
__device__ float g_V[BH*NS*HD];       // [bh][s][d]
__device__ float g_R[BH*NS*256];      // [(bh*1024+q)][256]
__device__ float g_AO[BH*NS*HD];      // [bh][s][d]

// ---------------- split helpers (registers only) ----------------
__device__ __forceinline__ uint32_t pack2bf(float a, float b) {
    __nv_bfloat162 t = __floats2bfloat162_rn(a, b);
    return *reinterpret_cast<uint32_t*>(&t);
}
__device__ __forceinline__ float bf_res(float a) {
    return a - __bfloat162float(__float2bfloat16(a));
}

// ---------------- shared MMA template pieces ----------------
#define SMS 40

#define MMA_OP(D, A, B0, B1)                                            \
    asm volatile(                                                       \
        "mma.sync.aligned.m16n8k16.row.col.f32.bf16.bf16.f32 "          \
        "{%0,%1,%2,%3}, {%4,%5,%6,%7}, {%8,%9}, {%0,%1,%2,%3};"         \
        : "+f"(D.x), "+f"(D.y), "+f"(D.z), "+f"(D.w)                    \
        : "r"(A.x), "r"(A.y), "r"(A.z), "r"(A.w), "r"(B0), "r"(B1))

#define LD32S(arr, idx) (*(const uint32_t*)&(arr)[idx])

#define NTSTEP(CA, CB, NT) {                                            \
    int rb_ = (wn*32 + (NT)*8 + g)*SMS + cc;                            \
    uint32_t b0h_ = LD32S(sBh, rb_), b1h_ = LD32S(sBh, rb_ + 8);        \
    uint32_t b0l_ = LD32S(sBl, rb_), b1l_ = LD32S(sBl, rb_ + 8);        \
    MMA_OP(CA, a0h, b0h_, b1h_); MMA_OP(CA, a0h, b0l_, b1l_);           \
    MMA_OP(CA, a0l, b0h_, b1h_);                                        \
    MMA_OP(CB, a1h, b0h_, b1h_); MMA_OP(CB, a1h, b0l_, b1l_);           \
    MMA_OP(CB, a1l, b0h_, b1h_); }

#define KSTEP(KK) {                                                     \
    const int cc = (KK) + tq*2;                                         \
    uint4 a0h, a1h, a0l, a1l;                                           \
    {   int ra_ = (wm*32 + g)*SMS + cc;                                 \
        a0h.x = LD32S(sAh, ra_);            a0h.y = LD32S(sAh, ra_ + 8*SMS); \
        a0h.z = LD32S(sAh, ra_ + 8);        a0h.w = LD32S(sAh, ra_ + 8*SMS + 8); \
        a0l.x = LD32S(sAl, ra_);            a0l.y = LD32S(sAl, ra_ + 8*SMS); \
        a0l.z = LD32S(sAl, ra_ + 8);        a0l.w = LD32S(sAl, ra_ + 8*SMS + 8); \
        int rb_ = ra_ + 16*SMS;                                         \
        a1h.x = LD32S(sAh, rb_);            a1h.y = LD32S(sAh, rb_ + 8*SMS); \
        a1h.z = LD32S(sAh, rb_ + 8);        a1h.w = LD32S(sAh, rb_ + 8*SMS + 8); \
        a1l.x = LD32S(sAl, rb_);            a1l.y = LD32S(sAl, rb_ + 8*SMS); \
        a1l.z = LD32S(sAl, rb_ + 8);        a1l.w = LD32S(sAl, rb_ + 8*SMS + 8); } \
    NTSTEP(c00, c10, 0); NTSTEP(c01, c11, 1);                           \
    NTSTEP(c02, c12, 2); NTSTEP(c03, c13, 3); }

#define STORE1(CMN, MT, NT) {                                           \
    int r_ = m0 + wm*32 + (MT)*16 + g;                                  \
    int c_ = n0 + wn*32 + (NT)*8 + tq*2;                                \
    float b0_ = bias[c_], b1_ = bias[c_+1];                             \
    *(float2*)&C[(size_t)r_ * N + c_] = make_float2(CMN.x + b0_, CMN.y + b1_); \
    *(float2*)&C[(size_t)(r_+8) * N + c_] = make_float2(CMN.z + b0_, CMN.w + b1_); }

// ---------------- GEMM1: qkv = x @ w_qkv + b (split-bf16 MMA, R10 proven) ----------------
__global__ __launch_bounds__(256)
void k_gemm1_mma(const float* __restrict__ X, const float* __restrict__ W,
                 const float* __restrict__ bias) {
    const int N = N3, K = 1024;
    __shared__ __align__(16) __nv_bfloat16 sAh[128*SMS], sAl[128*SMS];
    __shared__ __align__(16) __nv_bfloat16 sBh[64*SMS],  sBl[64*SMS];
    float* C = g_qkv;
    int t = threadIdx.x, lane = t & 31, warp = t >> 5;
    int wm = warp >> 1, wn = warp & 1;
    int g = lane >> 2, tq = lane & 3;
    int m0 = blockIdx.y * 128, n0 = blockIdx.x * 64;
    float4 c00 = make_float4(0.f,0.f,0.f,0.f), c01 = c00, c02 = c00, c03 = c00;
    float4 c10 = c00, c11 = c00, c12 = c00, c13 = c00;

    for (int k0 = 0; k0 < K; k0 += 32) {
#pragma unroll
        for (int p = 0; p < 4; p++) {
            int idx = t + p * 256;
            int row = idx >> 3, k4 = (idx & 7) << 2;
            float4 v = *(const float4*)&X[(size_t)(m0 + row) * K + k0 + k4];
            int so = row*SMS + k4;
            *(uint32_t*)&sAh[so]     = pack2bf(v.x, v.y);
            *(uint32_t*)&sAh[so + 2] = pack2bf(v.z, v.w);
            *(uint32_t*)&sAl[so]     = pack2bf(bf_res(v.x), bf_res(v.y));
            *(uint32_t*)&sAl[so + 2] = pack2bf(bf_res(v.z), bf_res(v.w));
        }
#pragma unroll
        for (int p = 0; p < 2; p++) {
            int idx = t + p * 256;
            int kr = idx >> 4, n4 = (idx & 15) << 2;
            float4 w = *(const float4*)&W[(size_t)(k0 + kr) * N + n0 + n4];
            sBh[(n4+0)*SMS + kr] = __float2bfloat16(w.x);
            sBh[(n4+1)*SMS + kr] = __float2bfloat16(w.y);
            sBh[(n4+2)*SMS + kr] = __float2bfloat16(w.z);
            sBh[(n4+3)*SMS + kr] = __float2bfloat16(w.w);
            sBl[(n4+0)*SMS + kr] = __float2bfloat16(bf_res(w.x));
            sBl[(n4+1)*SMS + kr] = __float2bfloat16(bf_res(w.y));
            sBl[(n4+2)*SMS + kr] = __float2bfloat16(bf_res(w.z));
            sBl[(n4+3)*SMS + kr] = __float2bfloat16(bf_res(w.w));
        }
        __syncthreads();
        KSTEP(0);
        KSTEP(16);
        __syncthreads();
    }
    STORE1(c00, 0, 0); STORE1(c01, 0, 1); STORE1(c02, 0, 2); STORE1(c03, 0, 3);
    STORE1(c10, 1, 0); STORE1(c11, 1, 1); STORE1(c12, 1, 2); STORE1(c13, 1, 3);
}

// ---------------- GEMM2: out = AO(hidden) @ w_out + b (split-bf16 MMA) ----------------
// A read from g_AO native [bh][s][d] via k' = h*64+d; B rows permuted r -> (r&63)*16 + r>>6.
__global__ __launch_bounds__(256)
void k_gemm2_mma(const float* __restrict__ W, const float* __restrict__ bias,
                 float* __restrict__ C) {
    const int N = 1024, K = 1024;
    __shared__ __align__(16) __nv_bfloat16 sAh[128*SMS], sAl[128*SMS];
    __shared__ __align__(16) __nv_bfloat16 sBh[64*SMS],  sBl[64*SMS];
    int t = threadIdx.x, lane = t & 31, warp = t >> 5;
    int wm = warp >> 1, wn = warp & 1;
    int g = lane >> 2, tq = lane & 3;
    int m0 = blockIdx.y * 128, n0 = blockIdx.x * 64;
    float4 c00 = make_float4(0.f,0.f,0.f,0.f), c01 = c00, c02 = c00, c03 = c00;
    float4 c10 = c00, c11 = c00, c12 = c00, c13 = c00;

    for (int k0 = 0; k0 < K; k0 += 32) {
        int h = k0 >> 6;             // k-slab of 32 stays within one head
        int dbase = k0 & 63;
#pragma unroll
        for (int p = 0; p < 4; p++) {
            int idx = t + p * 256;
            int row = idx >> 3, k4 = (idx & 7) << 2;
            int m = m0 + row;
            int ba = m >> 10, sa = m & 1023;
            float4 v = *(const float4*)&g_AO[((size_t)(ba*16 + h)*1024 + sa)*64 + dbase + k4];
            int so = row*SMS + k4;
            *(uint32_t*)&sAh[so]     = pack2bf(v.x, v.y);
            *(uint32_t*)&sAh[so + 2] = pack2bf(v.z, v.w);
            *(uint32_t*)&sAl[so]     = pack2bf(bf_res(v.x), bf_res(v.y));
            *(uint32_t*)&sAl[so + 2] = pack2bf(bf_res(v.z), bf_res(v.w));
        }
#pragma unroll
        for (int p = 0; p < 2; p++) {
            int idx = t + p * 256;
            int kr = idx >> 4, n4 = (idx & 15) << 2;
            int r = k0 + kr;
            int wr = ((r & 63) << 4) + (r >> 6);
            float4 w = *(const float4*)&W[(size_t)wr * N + n0 + n4];
            sBh[(n4+0)*SMS + kr] = __float2bfloat16(w.x);
            sBh[(n4+1)*SMS + kr] = __float2bfloat16(w.y);
            sBh[(n4+2)*SMS + kr] = __float2bfloat16(w.z);
            sBh[(n4+3)*SMS + kr] = __float2bfloat16(w.w);
            sBl[(n4+0)*SMS + kr] = __float2bfloat16(bf_res(w.x));
            sBl[(n4+1)*SMS + kr] = __float2bfloat16(bf_res(w.y));
            sBl[(n4+2)*SMS + kr] = __float2bfloat16(bf_res(w.z));
            sBl[(n4+3)*SMS + kr] = __float2bfloat16(bf_res(w.w));
        }
        __syncthreads();
        KSTEP(0);
        KSTEP(16);
        __syncthreads();
    }
    STORE1(c00, 0, 0); STORE1(c01, 0, 1); STORE1(c02, 0, 2); STORE1(c03, 0, 3);
    STORE1(c10, 1, 0); STORE1(c11, 1, 1); STORE1(c12, 1, 2); STORE1(c13, 1, 3);
}

// ---------------- rel: R[bh*1024+s][j] = sum_d Q.rel (split-bf16 MMA, K=64, no bias) ----------------
#define STORE0(CMN, MT, NT) {                                           \
    int r_ = mbase + wm*32 + (MT)*16 + g;                               \
    int c_ = n0 + wn*32 + (NT)*8 + tq*2;                                \
    *(float2*)&g_R[(size_t)r_ * 256 + c_] = make_float2(CMN.x, CMN.y);  \
    *(float2*)&g_R[(size_t)(r_+8) * 256 + c_] = make_float2(CMN.z, CMN.w); }

__global__ __launch_bounds__(256)
void k_rel_mma(const float* __restrict__ rel) {
    __shared__ __align__(16) __nv_bfloat16 sAh[128*SMS], sAl[128*SMS];
    __shared__ __align__(16) __nv_bfloat16 sBh[64*SMS],  sBl[64*SMS];
    int t = threadIdx.x, lane = t & 31, warp = t >> 5;
    int wm = warp >> 1, wn = warp & 1;
    int g = lane >> 2, tq = lane & 3;
    int mt = blockIdx.y;               // 0..511
    int bh = mt >> 3, s0t = (mt & 7) << 7;   // 128 s-rows within one bh
    int n0 = blockIdx.x * 64;
    int mbase = bh*1024 + s0t;
    float4 c00 = make_float4(0.f,0.f,0.f,0.f), c01 = c00, c02 = c00, c03 = c00;
    float4 c10 = c00, c11 = c00, c12 = c00, c13 = c00;

    for (int k0 = 0; k0 < 64; k0 += 32) {
        // A: g_Q [d][s] tile (32 d x 128 s) -> transposed smem [s][d], split inline
#pragma unroll
        for (int p = 0; p < 4; p++) {
            int idx = t + p * 256;
            int dl = idx >> 5, s4 = (idx & 31) << 2;
            float4 v = *(const float4*)&g_Q[(size_t)(bh*64 + k0 + dl)*1024 + s0t + s4];
            sAh[(s4+0)*SMS + dl] = __float2bfloat16(v.x);
            sAh[(s4+1)*SMS + dl] = __float2bfloat16(v.y);
            sAh[(s4+2)*SMS + dl] = __float2bfloat16(v.z);
            sAh[(s4+3)*SMS + dl] = __float2bfloat16(v.w);
            sAl[(s4+0)*SMS + dl] = __float2bfloat16(bf_res(v.x));
            sAl[(s4+1)*SMS + dl] = __float2bfloat16(bf_res(v.y));
            sAl[(s4+2)*SMS + dl] = __float2bfloat16(bf_res(v.z));
            sAl[(s4+3)*SMS + dl] = __float2bfloat16(bf_res(v.w));
        }
        // B: rel[j][d] K-major; zero-fill j >= 255 (table has 255 rows)
#pragma unroll
        for (int p = 0; p < 2; p++) {
            int idx = t + p * 256;
            int row = idx >> 3, k4 = (idx & 7) << 2;
            int j = n0 + row;
            float4 w = make_float4(0.f, 0.f, 0.f, 0.f);
            if (j < 255) w = *(const float4*)&rel[(size_t)j * 64 + k0 + k4];
            int so = row*SMS + k4;
            *(uint32_t*)&sBh[so]     = pack2bf(w.x, w.y);
            *(uint32_t*)&sBh[so + 2] = pack2bf(w.z, w.w);
            *(uint32_t*)&sBl[so]     = pack2bf(bf_res(w.x), bf_res(w.y));
            *(uint32_t*)&sBl[so + 2] = pack2bf(bf_res(w.z), bf_res(w.w));
        }
        __syncthreads();
        KSTEP(0);
        KSTEP(16);
        __syncthreads();
    }
    STORE0(c00, 0, 0); STORE0(c01, 0, 1); STORE0(c02, 0, 2); STORE0(c03, 0, 3);
    STORE0(c10, 1, 0); STORE0(c11, 1, 1); STORE0(c12, 1, 2); STORE0(c13, 1, 3);
}

// ---------------- repack qkv -> Q[bh][d][s], K[bh][d][s], V[bh][s][d] (R9) ----------------
__global__ __launch_bounds__(256)
void k_repack() {
    __shared__ float smem[64][68];
    int t = threadIdx.x;
    int c0 = blockIdx.x * 64, s0 = blockIdx.y * 64, b = blockIdx.z;
#pragma unroll
    for (int p = 0; p < 4; p++) {
        int lin = t + p * 256;
        int s = lin >> 4, c4 = (lin & 15) << 2;
        *(float4*)&smem[s][c4] = *(const float4*)&g_qkv[(size_t)(b*1024 + s0 + s)*N3 + c0 + c4];
    }
    __syncthreads();
    int chunk = c0 >> 10;
    int cw = c0 & 1023;
    int dB = cw >> 4;
    if (chunk < 2) {
        float* out = (chunk == 0) ? g_Q : g_K;
#pragma unroll
        for (int p = 0; p < 16; p++) {
            int w = t + p * 256;
            int cc = w >> 6, ss = w & 63;
            int d = dB + (cc >> 4), h = cc & 15;
            out[((b*16 + h)*64 + d)*1024 + s0 + ss] = smem[ss][cc];
        }
    } else {
#pragma unroll
        for (int p = 0; p < 4; p++) {
            int w = t + p * 256;
            int h = w >> 6, ss = w & 63;
            float4 v;
            v.x = smem[ss][h]; v.y = smem[ss][16+h]; v.z = smem[ss][32+h]; v.w = smem[ss][48+h];
            *(float4*)&g_V[((b*16 + h)*1024 + s0 + ss)*64 + dB] = v;
        }
    }
}

// ---------------- flash attention (R9: stride 64, KsT/Ps aliased, smem 114688) ----------------
__global__ __launch_bounds__(256, 1)
void k_attn(const int* __restrict__ mask) {
    extern __shared__ float sm[];
    float* QsT = sm;               // [d][q] s64
    float* KP  = sm + 4096;        // KsT / Ps aliased
    float* Vs  = sm + 8192;        // [k][d] s64
    float* Rs  = sm + 12288;       // [q][256]
    int t = threadIdx.x, tx = t & 15, ty = t >> 4;
    int qt = blockIdx.x, bh = blockIdx.y;
    int b = bh >> 4, q0 = qt << 6;
#pragma unroll
    for (int p = 0; p < 4; p++) {
        int lin = t + p * 256;
        int d = lin >> 4, c4 = (lin & 15) << 2;
        *(float4*)&QsT[d*64 + c4] = *(const float4*)&g_Q[(bh*64 + d)*1024 + q0 + c4];
    }
#pragma unroll
    for (int p = 0; p < 16; p++) {
        int lin = t + p * 256;
        int q = lin >> 6, j4 = (lin & 63) << 2;
        *(float4*)&Rs[q*256 + j4] = *(const float4*)&g_R[(size_t)(bh*1024 + q0 + q)*256 + j4];
    }
    float m_i[4], l_i[4], o[4][4];
#pragma unroll
    for (int i = 0; i < 4; i++) {
        m_i[i] = -INFINITY; l_i[i] = 0.f;
#pragma unroll
        for (int j = 0; j < 4; j++) o[i][j] = 0.f;
    }
    __syncthreads();
    for (int kt = 0; kt < 16; kt++) {
#pragma unroll
        for (int p = 0; p < 4; p++) {
            int lin = t + p * 256;
            int r = lin >> 4, c4 = (lin & 15) << 2;
            *(float4*)&KP[r*64 + c4] = *(const float4*)&g_K[(bh*64 + r)*1024 + kt*64 + c4];
            *(float4*)&Vs[r*64 + c4] = *(const float4*)&g_V[(size_t)(bh*1024 + kt*64 + r)*64 + c4];
        }
        __syncthreads();
        float s4[4][4];
#pragma unroll
        for (int i = 0; i < 4; i++)
#pragma unroll
            for (int j = 0; j < 4; j++) s4[i][j] = 0.f;
#pragma unroll 16
        for (int d = 0; d < 64; d++) {
            float4 aq = *(const float4*)&QsT[d*64 + ty*4];
            float4 bk = *(const float4*)&KP[d*64 + tx*4];
            s4[0][0] += aq.x*bk.x; s4[0][1] += aq.x*bk.y; s4[0][2] += aq.x*bk.z; s4[0][3] += aq.x*bk.w;
            s4[1][0] += aq.y*bk.x; s4[1][1] += aq.y*bk.y; s4[1][2] += aq.y*bk.z; s4[1][3] += aq.y*bk.w;
            s4[2][0] += aq.z*bk.x; s4[2][1] += aq.z*bk.y; s4[2][2] += aq.z*bk.z; s4[2][3] += aq.z*bk.w;
            s4[3][0] += aq.w*bk.x; s4[3][1] += aq.w*bk.y; s4[3][2] += aq.w*bk.z; s4[3][3] += aq.w*bk.w;
        }
        __syncthreads();
        int kg0 = kt*64 + tx*4;
#pragma unroll
        for (int i = 0; i < 4; i++) {
            int qg = q0 + ty*4 + i;
            int4 mv = *(const int4*)&mask[(size_t)(b*1024 + qg)*1024 + kg0];
            int mm[4] = {mv.x, mv.y, mv.z, mv.w};
            float sv[4];
#pragma unroll
            for (int j = 0; j < 4; j++) {
                int r = kg0 + j - qg;
                r = min(127, max(-127, r));
                float v = 8.0f * s4[i][j] + Rs[(ty*4 + i)*256 + r + 127];
                sv[j] = (mm[j] == 0) ? -1e8f : v;
            }
            float mx = fmaxf(fmaxf(sv[0], sv[1]), fmaxf(sv[2], sv[3]));
#pragma unroll
            for (int off = 8; off > 0; off >>= 1)
                mx = fmaxf(mx, __shfl_xor_sync(0xffffffffu, mx, off));
            float mnew = fmaxf(m_i[i], mx);
            float corr = __expf(m_i[i] - mnew);
            float p0 = __expf(sv[0] - mnew), p1 = __expf(sv[1] - mnew);
            float p2 = __expf(sv[2] - mnew), p3 = __expf(sv[3] - mnew);
            float sum = p0 + p1 + p2 + p3;
#pragma unroll
            for (int off = 8; off > 0; off >>= 1)
                sum += __shfl_xor_sync(0xffffffffu, sum, off);
            l_i[i] = l_i[i] * corr + sum;
            m_i[i] = mnew;
#pragma unroll
            for (int j = 0; j < 4; j++) o[i][j] *= corr;
            *(float4*)&KP[(ty*4 + i)*64 + tx*4] = make_float4(p0, p1, p2, p3);
        }
        __syncthreads();
#pragma unroll 16
        for (int k = 0; k < 64; k++) {
            float4 v4 = *(const float4*)&Vs[k*64 + tx*4];
            float pa0 = KP[(ty*4 + 0)*64 + k];
            float pa1 = KP[(ty*4 + 1)*64 + k];
            float pa2 = KP[(ty*4 + 2)*64 + k];
            float pa3 = KP[(ty*4 + 3)*64 + k];
            o[0][0] += pa0*v4.x; o[0][1] += pa0*v4.y; o[0][2] += pa0*v4.z; o[0][3] += pa0*v4.w;
            o[1][0] += pa1*v4.x; o[1][1] += pa1*v4.y; o[1][2] += pa1*v4.z; o[1][3] += pa1*v4.w;
            o[2][0] += pa2*v4.x; o[2][1] += pa2*v4.y; o[2][2] += pa2*v4.z; o[2][3] += pa2*v4.w;
            o[3][0] += pa3*v4.x; o[3][1] += pa3*v4.y; o[3][2] += pa3*v4.z; o[3][3] += pa3*v4.w;
        }
        __syncthreads();
    }
#pragma unroll
    for (int i = 0; i < 4; i++) {
        float inv = 1.0f / l_i[i];
        float4 w = make_float4(o[i][0]*inv, o[i][1]*inv, o[i][2]*inv, o[i][3]*inv);
        *(float4*)&g_AO[(size_t)(bh*1024 + q0 + ty*4 + i)*64 + tx*4] = w;
    }
}

extern "C" void kernel_launch(void* const* d_in, const int* in_sizes, int n_in,
                              void* d_out, int out_size) {
    const float* x     = (const float*)d_in[0];
    const int*   mask  = (const int*)  d_in[1];
    const float* w_qkv = (const float*)d_in[2];
    const float* b_qkv = (const float*)d_in[3];
    const float* rel   = (const float*)d_in[4];
    const float* w_out = (const float*)d_in[5];
    const float* b_out = (const float*)d_in[6];
    float* out = (float*)d_out;

    const int attnSmem = (3*64*64 + 64*256) * 4;   // 114688
    static int configured = 0;
    if (!configured) {
        cudaFuncSetAttribute(k_attn, cudaFuncAttributeMaxDynamicSharedMemorySize, attnSmem);
        configured = 1;
    }

    k_gemm1_mma<<<dim3(48, 32), 256>>>(x, w_qkv, b_qkv);
    k_repack   <<<dim3(48, 16, 4), 256>>>();
    k_rel_mma  <<<dim3(4, 512), 256>>>(rel);
    k_attn     <<<dim3(16, 64), 256, attnSmem>>>(mask);
    k_gemm2_mma<<<dim3(16, 32), 256>>>(w_out, b_out, out);
}

// round 13
// speedup vs baseline: 1.5880x; 1.2919x over previous
#include <cuda_runtime.h>
#include <cuda_bf16.h>
#include <math.h>
#include <stdint.h>

#define NB 4
#define NS 1024
#define NH 16
#define HD 64
#define BH (NB*NH)
#define N3 3072

// scratch (fp32 statics only)
__device__ float g_qkv[NB*NS*N3];     // [4096][3072]
__device__ float g_Q[BH*NS*HD];       // [bh][s][d]
__device__ float g_K[BH*NS*HD];       // [bh][s][d]
__device__ float g_Vt[BH*HD*NS];      // [bh][d][s]
__device__ float g_R[BH*NS*256];      // [(bh*1024+q)][256]
__device__ float g_AO[BH*NS*HD];      // [bh][s][d]

// ---------------- split helpers (registers only) ----------------
__device__ __forceinline__ uint32_t pack2bf(float a, float b) {
    __nv_bfloat162 t = __floats2bfloat162_rn(a, b);
    return *reinterpret_cast<uint32_t*>(&t);
}
__device__ __forceinline__ float bf_res(float a) {
    return a - __bfloat162float(__float2bfloat16(a));
}

// ---------------- shared MMA template pieces ----------------
#define SMS 40

#define MMA_OP(D, A, B0, B1)                                            \
    asm volatile(                                                       \
        "mma.sync.aligned.m16n8k16.row.col.f32.bf16.bf16.f32 "          \
        "{%0,%1,%2,%3}, {%4,%5,%6,%7}, {%8,%9}, {%0,%1,%2,%3};"         \
        : "+f"(D.x), "+f"(D.y), "+f"(D.z), "+f"(D.w)                    \
        : "r"(A.x), "r"(A.y), "r"(A.z), "r"(A.w), "r"(B0), "r"(B1))

#define LD32S(arr, idx) (*(const uint32_t*)&(arr)[idx])

#define NTSTEP(CA, CB, NT) {                                            \
    int rb_ = (wn*32 + (NT)*8 + g)*SMS + cc;                            \
    uint32_t b0h_ = LD32S(sBh, rb_), b1h_ = LD32S(sBh, rb_ + 8);        \
    uint32_t b0l_ = LD32S(sBl, rb_), b1l_ = LD32S(sBl, rb_ + 8);        \
    MMA_OP(CA, a0h, b0h_, b1h_); MMA_OP(CA, a0h, b0l_, b1l_);           \
    MMA_OP(CA, a0l, b0h_, b1h_);                                        \
    MMA_OP(CB, a1h, b0h_, b1h_); MMA_OP(CB, a1h, b0l_, b1l_);           \
    MMA_OP(CB, a1l, b0h_, b1h_); }

#define KSTEP(KK) {                                                     \
    const int cc = (KK) + tq*2;                                         \
    uint4 a0h, a1h, a0l, a1l;                                           \
    {   int ra_ = (wm*32 + g)*SMS + cc;                                 \
        a0h.x = LD32S(sAh, ra_);            a0h.y = LD32S(sAh, ra_ + 8*SMS); \
        a0h.z = LD32S(sAh, ra_ + 8);        a0h.w = LD32S(sAh, ra_ + 8*SMS + 8); \
        a0l.x = LD32S(sAl, ra_);            a0l.y = LD32S(sAl, ra_ + 8*SMS); \
        a0l.z = LD32S(sAl, ra_ + 8);        a0l.w = LD32S(sAl, ra_ + 8*SMS + 8); \
        int rb_ = ra_ + 16*SMS;                                         \
        a1h.x = LD32S(sAh, rb_);            a1h.y = LD32S(sAh, rb_ + 8*SMS); \
        a1h.z = LD32S(sAh, rb_ + 8);        a1h.w = LD32S(sAh, rb_ + 8*SMS + 8); \
        a1l.x = LD32S(sAl, rb_);            a1l.y = LD32S(sAl, rb_ + 8*SMS); \
        a1l.z = LD32S(sAl, rb_ + 8);        a1l.w = LD32S(sAl, rb_ + 8*SMS + 8); } \
    NTSTEP(c00, c10, 0); NTSTEP(c01, c11, 1);                           \
    NTSTEP(c02, c12, 2); NTSTEP(c03, c13, 3); }

#define STORE1(CMN, MT, NT) {                                           \
    int r_ = m0 + wm*32 + (MT)*16 + g;                                  \
    int c_ = n0 + wn*32 + (NT)*8 + tq*2;                                \
    float b0_ = bias[c_], b1_ = bias[c_+1];                             \
    *(float2*)&C[(size_t)r_ * N + c_] = make_float2(CMN.x + b0_, CMN.y + b1_); \
    *(float2*)&C[(size_t)(r_+8) * N + c_] = make_float2(CMN.z + b0_, CMN.w + b1_); }

// ---------------- GEMM1: qkv = x @ w_qkv + b (split-bf16 MMA, proven) ----------------
__global__ __launch_bounds__(256)
void k_gemm1_mma(const float* __restrict__ X, const float* __restrict__ W,
                 const float* __restrict__ bias) {
    const int N = N3, K = 1024;
    __shared__ __align__(16) __nv_bfloat16 sAh[128*SMS], sAl[128*SMS];
    __shared__ __align__(16) __nv_bfloat16 sBh[64*SMS],  sBl[64*SMS];
    float* C = g_qkv;
    int t = threadIdx.x, lane = t & 31, warp = t >> 5;
    int wm = warp >> 1, wn = warp & 1;
    int g = lane >> 2, tq = lane & 3;
    int m0 = blockIdx.y * 128, n0 = blockIdx.x * 64;
    float4 c00 = make_float4(0.f,0.f,0.f,0.f), c01 = c00, c02 = c00, c03 = c00;
    float4 c10 = c00, c11 = c00, c12 = c00, c13 = c00;

    for (int k0 = 0; k0 < K; k0 += 32) {
#pragma unroll
        for (int p = 0; p < 4; p++) {
            int idx = t + p * 256;
            int row = idx >> 3, k4 = (idx & 7) << 2;
            float4 v = *(const float4*)&X[(size_t)(m0 + row) * K + k0 + k4];
            int so = row*SMS + k4;
            *(uint32_t*)&sAh[so]     = pack2bf(v.x, v.y);
            *(uint32_t*)&sAh[so + 2] = pack2bf(v.z, v.w);
            *(uint32_t*)&sAl[so]     = pack2bf(bf_res(v.x), bf_res(v.y));
            *(uint32_t*)&sAl[so + 2] = pack2bf(bf_res(v.z), bf_res(v.w));
        }
#pragma unroll
        for (int p = 0; p < 2; p++) {
            int idx = t + p * 256;
            int kr = idx >> 4, n4 = (idx & 15) << 2;
            float4 w = *(const float4*)&W[(size_t)(k0 + kr) * N + n0 + n4];
            sBh[(n4+0)*SMS + kr] = __float2bfloat16(w.x);
            sBh[(n4+1)*SMS + kr] = __float2bfloat16(w.y);
            sBh[(n4+2)*SMS + kr] = __float2bfloat16(w.z);
            sBh[(n4+3)*SMS + kr] = __float2bfloat16(w.w);
            sBl[(n4+0)*SMS + kr] = __float2bfloat16(bf_res(w.x));
            sBl[(n4+1)*SMS + kr] = __float2bfloat16(bf_res(w.y));
            sBl[(n4+2)*SMS + kr] = __float2bfloat16(bf_res(w.z));
            sBl[(n4+3)*SMS + kr] = __float2bfloat16(bf_res(w.w));
        }
        __syncthreads();
        KSTEP(0);
        KSTEP(16);
        __syncthreads();
    }
    STORE1(c00, 0, 0); STORE1(c01, 0, 1); STORE1(c02, 0, 2); STORE1(c03, 0, 3);
    STORE1(c10, 1, 0); STORE1(c11, 1, 1); STORE1(c12, 1, 2); STORE1(c13, 1, 3);
}

// ---------------- GEMM2: out = AO(hidden) @ w_out + b (split-bf16 MMA, proven) ----------------
__global__ __launch_bounds__(256)
void k_gemm2_mma(const float* __restrict__ W, const float* __restrict__ bias,
                 float* __restrict__ C) {
    const int N = 1024, K = 1024;
    __shared__ __align__(16) __nv_bfloat16 sAh[128*SMS], sAl[128*SMS];
    __shared__ __align__(16) __nv_bfloat16 sBh[64*SMS],  sBl[64*SMS];
    int t = threadIdx.x, lane = t & 31, warp = t >> 5;
    int wm = warp >> 1, wn = warp & 1;
    int g = lane >> 2, tq = lane & 3;
    int m0 = blockIdx.y * 128, n0 = blockIdx.x * 64;
    float4 c00 = make_float4(0.f,0.f,0.f,0.f), c01 = c00, c02 = c00, c03 = c00;
    float4 c10 = c00, c11 = c00, c12 = c00, c13 = c00;

    for (int k0 = 0; k0 < K; k0 += 32) {
        int h = k0 >> 6;
        int dbase = k0 & 63;
#pragma unroll
        for (int p = 0; p < 4; p++) {
            int idx = t + p * 256;
            int row = idx >> 3, k4 = (idx & 7) << 2;
            int m = m0 + row;
            int ba = m >> 10, sa = m & 1023;
            float4 v = *(const float4*)&g_AO[((size_t)(ba*16 + h)*1024 + sa)*64 + dbase + k4];
            int so = row*SMS + k4;
            *(uint32_t*)&sAh[so]     = pack2bf(v.x, v.y);
            *(uint32_t*)&sAh[so + 2] = pack2bf(v.z, v.w);
            *(uint32_t*)&sAl[so]     = pack2bf(bf_res(v.x), bf_res(v.y));
            *(uint32_t*)&sAl[so + 2] = pack2bf(bf_res(v.z), bf_res(v.w));
        }
#pragma unroll
        for (int p = 0; p < 2; p++) {
            int idx = t + p * 256;
            int kr = idx >> 4, n4 = (idx & 15) << 2;
            int r = k0 + kr;
            int wr = ((r & 63) << 4) + (r >> 6);
            float4 w = *(const float4*)&W[(size_t)wr * N + n0 + n4];
            sBh[(n4+0)*SMS + kr] = __float2bfloat16(w.x);
            sBh[(n4+1)*SMS + kr] = __float2bfloat16(w.y);
            sBh[(n4+2)*SMS + kr] = __float2bfloat16(w.z);
            sBh[(n4+3)*SMS + kr] = __float2bfloat16(w.w);
            sBl[(n4+0)*SMS + kr] = __float2bfloat16(bf_res(w.x));
            sBl[(n4+1)*SMS + kr] = __float2bfloat16(bf_res(w.y));
            sBl[(n4+2)*SMS + kr] = __float2bfloat16(bf_res(w.z));
            sBl[(n4+3)*SMS + kr] = __float2bfloat16(bf_res(w.w));
        }
        __syncthreads();
        KSTEP(0);
        KSTEP(16);
        __syncthreads();
    }
    STORE1(c00, 0, 0); STORE1(c01, 0, 1); STORE1(c02, 0, 2); STORE1(c03, 0, 3);
    STORE1(c10, 1, 0); STORE1(c11, 1, 1); STORE1(c12, 1, 2); STORE1(c13, 1, 3);
}

// ---------------- rel: R = Q . rel^T (split-bf16 MMA; A now direct copy) ----------------
#define STORE0(CMN, MT, NT) {                                           \
    int r_ = mbase + wm*32 + (MT)*16 + g;                               \
    int c_ = n0 + wn*32 + (NT)*8 + tq*2;                                \
    *(float2*)&g_R[(size_t)r_ * 256 + c_] = make_float2(CMN.x, CMN.y);  \
    *(float2*)&g_R[(size_t)(r_+8) * 256 + c_] = make_float2(CMN.z, CMN.w); }

__global__ __launch_bounds__(256)
void k_rel_mma(const float* __restrict__ rel) {
    __shared__ __align__(16) __nv_bfloat16 sAh[128*SMS], sAl[128*SMS];
    __shared__ __align__(16) __nv_bfloat16 sBh[64*SMS],  sBl[64*SMS];
    int t = threadIdx.x, lane = t & 31, warp = t >> 5;
    int wm = warp >> 1, wn = warp & 1;
    int g = lane >> 2, tq = lane & 3;
    int mt = blockIdx.y;
    int bh = mt >> 3, s0t = (mt & 7) << 7;
    int n0 = blockIdx.x * 64;
    int mbase = bh*1024 + s0t;
    float4 c00 = make_float4(0.f,0.f,0.f,0.f), c01 = c00, c02 = c00, c03 = c00;
    float4 c10 = c00, c11 = c00, c12 = c00, c13 = c00;

    for (int k0 = 0; k0 < 64; k0 += 32) {
        // A: g_Q [bh][s][d] direct copy, split inline
#pragma unroll
        for (int p = 0; p < 4; p++) {
            int idx = t + p * 256;
            int row = idx >> 3, k4 = (idx & 7) << 2;
            float4 v = *(const float4*)&g_Q[(size_t)(bh*1024 + s0t + row)*64 + k0 + k4];
            int so = row*SMS + k4;
            *(uint32_t*)&sAh[so]     = pack2bf(v.x, v.y);
            *(uint32_t*)&sAh[so + 2] = pack2bf(v.z, v.w);
            *(uint32_t*)&sAl[so]     = pack2bf(bf_res(v.x), bf_res(v.y));
            *(uint32_t*)&sAl[so + 2] = pack2bf(bf_res(v.z), bf_res(v.w));
        }
        // B: rel[j][d] K-major; zero-fill j >= 255
#pragma unroll
        for (int p = 0; p < 2; p++) {
            int idx = t + p * 256;
            int row = idx >> 3, k4 = (idx & 7) << 2;
            int j = n0 + row;
            float4 w = make_float4(0.f, 0.f, 0.f, 0.f);
            if (j < 255) w = *(const float4*)&rel[(size_t)j * 64 + k0 + k4];
            int so = row*SMS + k4;
            *(uint32_t*)&sBh[so]     = pack2bf(w.x, w.y);
            *(uint32_t*)&sBh[so + 2] = pack2bf(w.z, w.w);
            *(uint32_t*)&sBl[so]     = pack2bf(bf_res(w.x), bf_res(w.y));
            *(uint32_t*)&sBl[so + 2] = pack2bf(bf_res(w.z), bf_res(w.w));
        }
        __syncthreads();
        KSTEP(0);
        KSTEP(16);
        __syncthreads();
    }
    STORE0(c00, 0, 0); STORE0(c01, 0, 1); STORE0(c02, 0, 2); STORE0(c03, 0, 3);
    STORE0(c10, 1, 0); STORE0(c11, 1, 1); STORE0(c12, 1, 2); STORE0(c13, 1, 3);
}

// ---------------- repack qkv -> Q[bh][s][d], K[bh][s][d], Vt[bh][d][s] ----------------
__global__ __launch_bounds__(256)
void k_repack() {
    __shared__ float smem[64][68];
    int t = threadIdx.x;
    int c0 = blockIdx.x * 64, s0 = blockIdx.y * 64, b = blockIdx.z;
#pragma unroll
    for (int p = 0; p < 4; p++) {
        int lin = t + p * 256;
        int s = lin >> 4, c4 = (lin & 15) << 2;
        *(float4*)&smem[s][c4] = *(const float4*)&g_qkv[(size_t)(b*1024 + s0 + s)*N3 + c0 + c4];
    }
    __syncthreads();
    int chunk = c0 >> 10;
    int cw = c0 & 1023;
    int dB = cw >> 4;
    if (chunk < 2) {
        float* out = (chunk == 0) ? g_Q : g_K;   // [bh][s][d]
#pragma unroll
        for (int p = 0; p < 4; p++) {
            int w = t + p * 256;
            int h = w >> 6, ss = w & 63;
            float4 v;
            v.x = smem[ss][h]; v.y = smem[ss][16+h]; v.z = smem[ss][32+h]; v.w = smem[ss][48+h];
            *(float4*)&out[((size_t)(b*16 + h)*1024 + s0 + ss)*64 + dB] = v;
        }
    } else {
        // V -> transposed [bh][d][s]
#pragma unroll
        for (int p = 0; p < 16; p++) {
            int w = t + p * 256;
            int cc = w >> 6, ss = w & 63;
            int d = dB + (cc >> 4), h = cc & 15;
            g_Vt[((size_t)(b*16 + h)*64 + d)*1024 + s0 + ss] = smem[ss][cc];
        }
    }
}

// ---------------- attention: split-bf16 MMA flash kernel ----------------
// 8 warps = 4(q) x 2(k-half). Warp tile 16q x 32k. Q frags in registers.
__global__ __launch_bounds__(256)
void k_attn_mma(const int* __restrict__ mask) {
    __shared__ __align__(16) __nv_bfloat16 sKh[64*72], sKl[64*72];
    __shared__ __align__(16) __nv_bfloat16 sVh[64*72], sVl[64*72];
    __shared__ float sMax[128], sSum[128];
    int t = threadIdx.x, lane = t & 31, warp = t >> 5;
    int wq = warp >> 1, wk = warp & 1;
    int g = lane >> 2, tq = lane & 3;
    int qt = blockIdx.x, bh = blockIdx.y;
    int b = bh >> 4, q0 = qt << 6;
    int qloc = wq*16 + g;
    int qg = q0 + qloc;
    size_t bhq = (size_t)bh * 1024;

    // Q fragments (whole-kernel registers), split hi/lo
    uint4 qh[4], ql[4];
#pragma unroll
    for (int kk = 0; kk < 4; kk++) {
        int cc = kk*16 + tq*2;
        float2 v00 = *(const float2*)&g_Q[(bhq + qg)*64 + cc];
        float2 v10 = *(const float2*)&g_Q[(bhq + qg + 8)*64 + cc];
        float2 v01 = *(const float2*)&g_Q[(bhq + qg)*64 + cc + 8];
        float2 v11 = *(const float2*)&g_Q[(bhq + qg + 8)*64 + cc + 8];
        qh[kk].x = pack2bf(v00.x, v00.y); ql[kk].x = pack2bf(bf_res(v00.x), bf_res(v00.y));
        qh[kk].y = pack2bf(v10.x, v10.y); ql[kk].y = pack2bf(bf_res(v10.x), bf_res(v10.y));
        qh[kk].z = pack2bf(v01.x, v01.y); ql[kk].z = pack2bf(bf_res(v01.x), bf_res(v01.y));
        qh[kk].w = pack2bf(v11.x, v11.y); ql[kk].w = pack2bf(bf_res(v11.x), bf_res(v11.y));
    }

    float4 o[8];
#pragma unroll
    for (int i = 0; i < 8; i++) o[i] = make_float4(0.f, 0.f, 0.f, 0.f);
    float m0 = -INFINITY, m1 = -INFINITY, l0 = 0.f, l1 = 0.f;

    const float* Rq  = g_R + (bhq + qg) * 256;
    const float* Rq8 = g_R + (bhq + qg + 8) * 256;
    const int* Mq  = mask + ((size_t)b*1024 + qg) * 1024;
    const int* Mq8 = mask + ((size_t)b*1024 + qg + 8) * 1024;

    for (int kt = 0; kt < 16; kt++) {
        int ktb = kt * 64;
        // fills: K [key][d], Vt [d][key], both split
#pragma unroll
        for (int p = 0; p < 4; p++) {
            int id = t + p * 256;
            int row = id >> 4, c4 = (id & 15) << 2;
            float4 v = *(const float4*)&g_K[(bhq + ktb + row)*64 + c4];
            *(uint32_t*)&sKh[row*72 + c4]     = pack2bf(v.x, v.y);
            *(uint32_t*)&sKh[row*72 + c4 + 2] = pack2bf(v.z, v.w);
            *(uint32_t*)&sKl[row*72 + c4]     = pack2bf(bf_res(v.x), bf_res(v.y));
            *(uint32_t*)&sKl[row*72 + c4 + 2] = pack2bf(bf_res(v.z), bf_res(v.w));
            float4 w = *(const float4*)&g_Vt[((size_t)bh*64 + row)*1024 + ktb + c4];
            *(uint32_t*)&sVh[row*72 + c4]     = pack2bf(w.x, w.y);
            *(uint32_t*)&sVh[row*72 + c4 + 2] = pack2bf(w.z, w.w);
            *(uint32_t*)&sVl[row*72 + c4]     = pack2bf(bf_res(w.x), bf_res(w.y));
            *(uint32_t*)&sVl[row*72 + c4 + 2] = pack2bf(bf_res(w.z), bf_res(w.w));
        }
        __syncthreads();

        // QK^T: S (16q x 32k), 4 n-tiles, split-3
        float4 s4[4];
#pragma unroll
        for (int i = 0; i < 4; i++) s4[i] = make_float4(0.f, 0.f, 0.f, 0.f);
#pragma unroll
        for (int nt = 0; nt < 4; nt++) {
            int rowb = (wk*32 + nt*8 + g)*72;
#pragma unroll
            for (int kk = 0; kk < 4; kk++) {
                int cc = rowb + kk*16 + tq*2;
                uint32_t b0h = LD32S(sKh, cc), b1h = LD32S(sKh, cc + 8);
                uint32_t b0l = LD32S(sKl, cc), b1l = LD32S(sKl, cc + 8);
                MMA_OP(s4[nt], qh[kk], b0h, b1h);
                MMA_OP(s4[nt], qh[kk], b0l, b1l);
                MMA_OP(s4[nt], ql[kk], b0h, b1h);
            }
        }

        // bias + mask
        int kb = ktb + wk*32;
#pragma unroll
        for (int nt = 0; nt < 4; nt++) {
            int kg = kb + nt*8 + tq*2;
            int rx = min(127, max(-127, kg - qg)) + 127;
            int ry = min(127, max(-127, kg + 1 - qg)) + 127;
            int rz = min(127, max(-127, kg - qg - 8)) + 127;
            int rw = min(127, max(-127, kg + 1 - qg - 8)) + 127;
            int2 mv0 = *(const int2*)&Mq[kg];
            int2 mv1 = *(const int2*)&Mq8[kg];
            s4[nt].x = (mv0.x == 0) ? -1e8f : 8.f*s4[nt].x + __ldg(&Rq[rx]);
            s4[nt].y = (mv0.y == 0) ? -1e8f : 8.f*s4[nt].y + __ldg(&Rq[ry]);
            s4[nt].z = (mv1.x == 0) ? -1e8f : 8.f*s4[nt].z + __ldg(&Rq8[rz]);
            s4[nt].w = (mv1.y == 0) ? -1e8f : 8.f*s4[nt].w + __ldg(&Rq8[rw]);
        }

        // row max (warp part, then cross-warp)
        float mg  = fmaxf(fmaxf(s4[0].x, s4[0].y), fmaxf(s4[1].x, s4[1].y));
        mg = fmaxf(mg, fmaxf(fmaxf(s4[2].x, s4[2].y), fmaxf(s4[3].x, s4[3].y)));
        float mg8 = fmaxf(fmaxf(s4[0].z, s4[0].w), fmaxf(s4[1].z, s4[1].w));
        mg8 = fmaxf(mg8, fmaxf(fmaxf(s4[2].z, s4[2].w), fmaxf(s4[3].z, s4[3].w)));
        mg  = fmaxf(mg,  __shfl_xor_sync(0xffffffffu, mg, 1));
        mg  = fmaxf(mg,  __shfl_xor_sync(0xffffffffu, mg, 2));
        mg8 = fmaxf(mg8, __shfl_xor_sync(0xffffffffu, mg8, 1));
        mg8 = fmaxf(mg8, __shfl_xor_sync(0xffffffffu, mg8, 2));
        if (tq == 0) { sMax[wk*64 + qloc] = mg; sMax[wk*64 + qloc + 8] = mg8; }
        __syncthreads();
        float mn0 = fmaxf(m0, fmaxf(sMax[qloc], sMax[64 + qloc]));
        float mn1 = fmaxf(m1, fmaxf(sMax[qloc + 8], sMax[64 + qloc + 8]));
        float cr0 = __expf(m0 - mn0), cr1 = __expf(m1 - mn1);

        // exp + row sums
        float sg = 0.f, sg8 = 0.f;
#pragma unroll
        for (int nt = 0; nt < 4; nt++) {
            s4[nt].x = __expf(s4[nt].x - mn0); s4[nt].y = __expf(s4[nt].y - mn0);
            s4[nt].z = __expf(s4[nt].z - mn1); s4[nt].w = __expf(s4[nt].w - mn1);
            sg  += s4[nt].x + s4[nt].y;
            sg8 += s4[nt].z + s4[nt].w;
        }
        sg  += __shfl_xor_sync(0xffffffffu, sg, 1);  sg  += __shfl_xor_sync(0xffffffffu, sg, 2);
        sg8 += __shfl_xor_sync(0xffffffffu, sg8, 1); sg8 += __shfl_xor_sync(0xffffffffu, sg8, 2);
        if (tq == 0) { sSum[wk*64 + qloc] = sg; sSum[wk*64 + qloc + 8] = sg8; }
        __syncthreads();
        l0 = l0*cr0 + sSum[qloc] + sSum[64 + qloc];
        l1 = l1*cr1 + sSum[qloc + 8] + sSum[64 + qloc + 8];
        m0 = mn0; m1 = mn1;
#pragma unroll
        for (int i = 0; i < 8; i++) { o[i].x *= cr0; o[i].y *= cr0; o[i].z *= cr1; o[i].w *= cr1; }

        // P fragments (C-layout == A-layout), split hi/lo
        uint4 pa0h, pa0l, pa1h, pa1l;
        pa0h.x = pack2bf(s4[0].x, s4[0].y); pa0h.y = pack2bf(s4[0].z, s4[0].w);
        pa0h.z = pack2bf(s4[1].x, s4[1].y); pa0h.w = pack2bf(s4[1].z, s4[1].w);
        pa1h.x = pack2bf(s4[2].x, s4[2].y); pa1h.y = pack2bf(s4[2].z, s4[2].w);
        pa1h.z = pack2bf(s4[3].x, s4[3].y); pa1h.w = pack2bf(s4[3].z, s4[3].w);
        pa0l.x = pack2bf(bf_res(s4[0].x), bf_res(s4[0].y)); pa0l.y = pack2bf(bf_res(s4[0].z), bf_res(s4[0].w));
        pa0l.z = pack2bf(bf_res(s4[1].x), bf_res(s4[1].y)); pa0l.w = pack2bf(bf_res(s4[1].z), bf_res(s4[1].w));
        pa1l.x = pack2bf(bf_res(s4[2].x), bf_res(s4[2].y)); pa1l.y = pack2bf(bf_res(s4[2].z), bf_res(s4[2].w));
        pa1l.z = pack2bf(bf_res(s4[3].x), bf_res(s4[3].y)); pa1l.w = pack2bf(bf_res(s4[3].z), bf_res(s4[3].w));

        // P @ V: O (16q x 64d), 8 n-tiles (d), split-3
#pragma unroll
        for (int nt = 0; nt < 8; nt++) {
            int rb = (nt*8 + g)*72 + wk*32;
            {
                int cc = rb + tq*2;
                uint32_t b0h = LD32S(sVh, cc), b1h = LD32S(sVh, cc + 8);
                uint32_t b0l = LD32S(sVl, cc), b1l = LD32S(sVl, cc + 8);
                MMA_OP(o[nt], pa0h, b0h, b1h);
                MMA_OP(o[nt], pa0h, b0l, b1l);
                MMA_OP(o[nt], pa0l, b0h, b1h);
            }
            {
                int cc = rb + 16 + tq*2;
                uint32_t b0h = LD32S(sVh, cc), b1h = LD32S(sVh, cc + 8);
                uint32_t b0l = LD32S(sVl, cc), b1l = LD32S(sVl, cc + 8);
                MMA_OP(o[nt], pa1h, b0h, b1h);
                MMA_OP(o[nt], pa1h, b0l, b1l);
                MMA_OP(o[nt], pa1l, b0h, b1h);
            }
        }
        __syncthreads();   // protect K/V smem before next fill
    }

    // combine the two k-warp halves via smem (alias over sKh/sKl), then write
    float* sO = (float*)sKh;
    if (wk == 0) {
#pragma unroll
        for (int nt = 0; nt < 8; nt++) {
            *(float2*)&sO[qloc*64 + nt*8 + tq*2]       = make_float2(o[nt].x, o[nt].y);
            *(float2*)&sO[(qloc + 8)*64 + nt*8 + tq*2] = make_float2(o[nt].z, o[nt].w);
        }
    }
    __syncthreads();
    if (wk == 1) {
        float inv0 = 1.f / l0, inv1 = 1.f / l1;
#pragma unroll
        for (int nt = 0; nt < 8; nt++) {
            float2 a  = *(float2*)&sO[qloc*64 + nt*8 + tq*2];
            float2 a8 = *(float2*)&sO[(qloc + 8)*64 + nt*8 + tq*2];
            *(float2*)&g_AO[(bhq + qg)*64 + nt*8 + tq*2] =
                make_float2((a.x + o[nt].x)*inv0, (a.y + o[nt].y)*inv0);
            *(float2*)&g_AO[(bhq + qg + 8)*64 + nt*8 + tq*2] =
                make_float2((a8.x + o[nt].z)*inv1, (a8.y + o[nt].w)*inv1);
        }
    }
}

extern "C" void kernel_launch(void* const* d_in, const int* in_sizes, int n_in,
                              void* d_out, int out_size) {
    const float* x     = (const float*)d_in[0];
    const int*   mask  = (const int*)  d_in[1];
    const float* w_qkv = (const float*)d_in[2];
    const float* b_qkv = (const float*)d_in[3];
    const float* rel   = (const float*)d_in[4];
    const float* w_out = (const float*)d_in[5];
    const float* b_out = (const float*)d_in[6];
    float* out = (float*)d_out;

    k_gemm1_mma<<<dim3(48, 32), 256>>>(x, w_qkv, b_qkv);
    k_repack   <<<dim3(48, 16, 4), 256>>>();
    k_rel_mma  <<<dim3(4, 512), 256>>>(rel);
    k_attn_mma <<<dim3(16, 64), 256>>>(mask);
    k_gemm2_mma<<<dim3(16, 32), 256>>>(w_out, b_out, out);
}

// round 15
// speedup vs baseline: 1.6215x; 1.0211x over previous
#include <cuda_runtime.h>
#include <cuda_bf16.h>
#include <math.h>
#include <stdint.h>

#define NB 4
#define NS 1024
#define NH 16
#define HD 64
#define BH (NB*NH)
#define N3 3072

// scratch (fp32 statics only)
__device__ float g_qkv[NB*NS*N3];     // [4096][3072]
__device__ float g_Q[BH*NS*HD];       // [bh][s][d]
__device__ float g_K[BH*NS*HD];       // [bh][s][d]
__device__ float g_Vt[BH*HD*NS];      // [bh][d][s]
__device__ float g_R[BH*NS*256];      // [(bh*1024+q)][256]
__device__ float g_AO[BH*NS*HD];      // [bh][s][d]

// ---------------- split helpers (registers only) ----------------
__device__ __forceinline__ uint32_t pack2bf(float a, float b) {
    __nv_bfloat162 t = __floats2bfloat162_rn(a, b);
    return *reinterpret_cast<uint32_t*>(&t);
}
__device__ __forceinline__ float bf_res(float a) {
    return a - __bfloat162float(__float2bfloat16(a));
}

// ---------------- shared MMA template pieces ----------------
#define SMS 40

#define MMA_OP(D, A, B0, B1)                                            \
    asm volatile(                                                       \
        "mma.sync.aligned.m16n8k16.row.col.f32.bf16.bf16.f32 "          \
        "{%0,%1,%2,%3}, {%4,%5,%6,%7}, {%8,%9}, {%0,%1,%2,%3};"         \
        : "+f"(D.x), "+f"(D.y), "+f"(D.z), "+f"(D.w)                    \
        : "r"(A.x), "r"(A.y), "r"(A.z), "r"(A.w), "r"(B0), "r"(B1))

#define LD32S(arr, idx) (*(const uint32_t*)&(arr)[idx])

#define LDM_X4(D, ADDR)                                                 \
    asm volatile("ldmatrix.sync.aligned.m8n8.x4.shared.b16 "            \
        "{%0,%1,%2,%3}, [%4];"                                          \
        : "=r"(D.x), "=r"(D.y), "=r"(D.z), "=r"(D.w) : "r"(ADDR))

// Per-lane ldmatrix base offsets: row = lane&15, k-half = lane>>4.
// A tiles: rows wm*32 + {0..15} and +16; B tiles: rows wn*32 + {0..15} and +16.
#define LDM_SETUP()                                                     \
    uint32_t _ao = (uint32_t)(((wm*32 + (lane & 15))*SMS + (lane >> 4)*8) * 2); \
    uint32_t _bo = (uint32_t)(((wn*32 + (lane & 15))*SMS + (lane >> 4)*8) * 2); \
    uint32_t pA0h = (uint32_t)__cvta_generic_to_shared(sAh) + _ao;      \
    uint32_t pA1h = pA0h + 16*SMS*2;                                    \
    uint32_t pA0l = (uint32_t)__cvta_generic_to_shared(sAl) + _ao;      \
    uint32_t pA1l = pA0l + 16*SMS*2;                                    \
    uint32_t pB0h = (uint32_t)__cvta_generic_to_shared(sBh) + _bo;      \
    uint32_t pB1h = pB0h + 16*SMS*2;                                    \
    uint32_t pB0l = (uint32_t)__cvta_generic_to_shared(sBl) + _bo;      \
    uint32_t pB1l = pB0l + 16*SMS*2;

// B x4 mapping: (x,z) = n-tile0 {b0,b1}; (y,w) = n-tile1.
#define KSTEP(KK) {                                                     \
    uint4 a0h, a1h, a0l, a1l, b01h, b23h, b01l, b23l;                   \
    LDM_X4(a0h, pA0h + (KK)*2); LDM_X4(a1h, pA1h + (KK)*2);             \
    LDM_X4(a0l, pA0l + (KK)*2); LDM_X4(a1l, pA1l + (KK)*2);             \
    LDM_X4(b01h, pB0h + (KK)*2); LDM_X4(b23h, pB1h + (KK)*2);           \
    LDM_X4(b01l, pB0l + (KK)*2); LDM_X4(b23l, pB1l + (KK)*2);           \
    MMA_OP(c00, a0h, b01h.x, b01h.z); MMA_OP(c00, a0h, b01l.x, b01l.z); MMA_OP(c00, a0l, b01h.x, b01h.z); \
    MMA_OP(c10, a1h, b01h.x, b01h.z); MMA_OP(c10, a1h, b01l.x, b01l.z); MMA_OP(c10, a1l, b01h.x, b01h.z); \
    MMA_OP(c01, a0h, b01h.y, b01h.w); MMA_OP(c01, a0h, b01l.y, b01l.w); MMA_OP(c01, a0l, b01h.y, b01h.w); \
    MMA_OP(c11, a1h, b01h.y, b01h.w); MMA_OP(c11, a1h, b01l.y, b01l.w); MMA_OP(c11, a1l, b01h.y, b01h.w); \
    MMA_OP(c02, a0h, b23h.x, b23h.z); MMA_OP(c02, a0h, b23l.x, b23l.z); MMA_OP(c02, a0l, b23h.x, b23h.z); \
    MMA_OP(c12, a1h, b23h.x, b23h.z); MMA_OP(c12, a1h, b23l.x, b23l.z); MMA_OP(c12, a1l, b23h.x, b23h.z); \
    MMA_OP(c03, a0h, b23h.y, b23h.w); MMA_OP(c03, a0h, b23l.y, b23l.w); MMA_OP(c03, a0l, b23h.y, b23h.w); \
    MMA_OP(c13, a1h, b23h.y, b23h.w); MMA_OP(c13, a1h, b23l.y, b23l.w); MMA_OP(c13, a1l, b23h.y, b23h.w); \
}

#define STORE1(CMN, MT, NT) {                                           \
    int r_ = m0 + wm*32 + (MT)*16 + g;                                  \
    int c_ = n0 + wn*32 + (NT)*8 + tq*2;                                \
    float b0_ = bias[c_], b1_ = bias[c_+1];                             \
    *(float2*)&C[(size_t)r_ * N + c_] = make_float2(CMN.x + b0_, CMN.y + b1_); \
    *(float2*)&C[(size_t)(r_+8) * N + c_] = make_float2(CMN.z + b0_, CMN.w + b1_); }

// ---------------- GEMM1: qkv = x @ w_qkv + b ----------------
__global__ __launch_bounds__(256)
void k_gemm1_mma(const float* __restrict__ X, const float* __restrict__ W,
                 const float* __restrict__ bias) {
    const int N = N3, K = 1024;
    __shared__ __align__(16) __nv_bfloat16 sAh[128*SMS], sAl[128*SMS];
    __shared__ __align__(16) __nv_bfloat16 sBh[64*SMS],  sBl[64*SMS];
    float* C = g_qkv;
    int t = threadIdx.x, lane = t & 31, warp = t >> 5;
    int wm = warp >> 1, wn = warp & 1;
    int g = lane >> 2, tq = lane & 3;
    int m0 = blockIdx.y * 128, n0 = blockIdx.x * 64;
    LDM_SETUP();
    float4 c00 = make_float4(0.f,0.f,0.f,0.f), c01 = c00, c02 = c00, c03 = c00;
    float4 c10 = c00, c11 = c00, c12 = c00, c13 = c00;

    for (int k0 = 0; k0 < K; k0 += 32) {
#pragma unroll
        for (int p = 0; p < 4; p++) {
            int idx = t + p * 256;
            int row = idx >> 3, k4 = (idx & 7) << 2;
            float4 v = *(const float4*)&X[(size_t)(m0 + row) * K + k0 + k4];
            int so = row*SMS + k4;
            *(uint32_t*)&sAh[so]     = pack2bf(v.x, v.y);
            *(uint32_t*)&sAh[so + 2] = pack2bf(v.z, v.w);
            *(uint32_t*)&sAl[so]     = pack2bf(bf_res(v.x), bf_res(v.y));
            *(uint32_t*)&sAl[so + 2] = pack2bf(bf_res(v.z), bf_res(v.w));
        }
#pragma unroll
        for (int p = 0; p < 2; p++) {
            int idx = t + p * 256;
            int kr = idx >> 4, n4 = (idx & 15) << 2;
            float4 w = *(const float4*)&W[(size_t)(k0 + kr) * N + n0 + n4];
            sBh[(n4+0)*SMS + kr] = __float2bfloat16(w.x);
            sBh[(n4+1)*SMS + kr] = __float2bfloat16(w.y);
            sBh[(n4+2)*SMS + kr] = __float2bfloat16(w.z);
            sBh[(n4+3)*SMS + kr] = __float2bfloat16(w.w);
            sBl[(n4+0)*SMS + kr] = __float2bfloat16(bf_res(w.x));
            sBl[(n4+1)*SMS + kr] = __float2bfloat16(bf_res(w.y));
            sBl[(n4+2)*SMS + kr] = __float2bfloat16(bf_res(w.z));
            sBl[(n4+3)*SMS + kr] = __float2bfloat16(bf_res(w.w));
        }
        __syncthreads();
        KSTEP(0);
        KSTEP(16);
        __syncthreads();
    }
    STORE1(c00, 0, 0); STORE1(c01, 0, 1); STORE1(c02, 0, 2); STORE1(c03, 0, 3);
    STORE1(c10, 1, 0); STORE1(c11, 1, 1); STORE1(c12, 1, 2); STORE1(c13, 1, 3);
}

// ---------------- GEMM2: out = AO(hidden) @ w_out + b ----------------
__global__ __launch_bounds__(256)
void k_gemm2_mma(const float* __restrict__ W, const float* __restrict__ bias,
                 float* __restrict__ C) {
    const int N = 1024, K = 1024;
    __shared__ __align__(16) __nv_bfloat16 sAh[128*SMS], sAl[128*SMS];
    __shared__ __align__(16) __nv_bfloat16 sBh[64*SMS],  sBl[64*SMS];
    int t = threadIdx.x, lane = t & 31, warp = t >> 5;
    int wm = warp >> 1, wn = warp & 1;
    int g = lane >> 2, tq = lane & 3;
    int m0 = blockIdx.y * 128, n0 = blockIdx.x * 64;
    LDM_SETUP();
    float4 c00 = make_float4(0.f,0.f,0.f,0.f), c01 = c00, c02 = c00, c03 = c00;
    float4 c10 = c00, c11 = c00, c12 = c00, c13 = c00;

    for (int k0 = 0; k0 < K; k0 += 32) {
        int h = k0 >> 6;
        int dbase = k0 & 63;
#pragma unroll
        for (int p = 0; p < 4; p++) {
            int idx = t + p * 256;
            int row = idx >> 3, k4 = (idx & 7) << 2;
            int m = m0 + row;
            int ba = m >> 10, sa = m & 1023;
            float4 v = *(const float4*)&g_AO[((size_t)(ba*16 + h)*1024 + sa)*64 + dbase + k4];
            int so = row*SMS + k4;
            *(uint32_t*)&sAh[so]     = pack2bf(v.x, v.y);
            *(uint32_t*)&sAh[so + 2] = pack2bf(v.z, v.w);
            *(uint32_t*)&sAl[so]     = pack2bf(bf_res(v.x), bf_res(v.y));
            *(uint32_t*)&sAl[so + 2] = pack2bf(bf_res(v.z), bf_res(v.w));
        }
#pragma unroll
        for (int p = 0; p < 2; p++) {
            int idx = t + p * 256;
            int kr = idx >> 4, n4 = (idx & 15) << 2;
            int r = k0 + kr;
            int wr = ((r & 63) << 4) + (r >> 6);
            float4 w = *(const float4*)&W[(size_t)wr * N + n0 + n4];
            sBh[(n4+0)*SMS + kr] = __float2bfloat16(w.x);
            sBh[(n4+1)*SMS + kr] = __float2bfloat16(w.y);
            sBh[(n4+2)*SMS + kr] = __float2bfloat16(w.z);
            sBh[(n4+3)*SMS + kr] = __float2bfloat16(w.w);
            sBl[(n4+0)*SMS + kr] = __float2bfloat16(bf_res(w.x));
            sBl[(n4+1)*SMS + kr] = __float2bfloat16(bf_res(w.y));
            sBl[(n4+2)*SMS + kr] = __float2bfloat16(bf_res(w.z));
            sBl[(n4+3)*SMS + kr] = __float2bfloat16(bf_res(w.w));
        }
        __syncthreads();
        KSTEP(0);
        KSTEP(16);
        __syncthreads();
    }
    STORE1(c00, 0, 0); STORE1(c01, 0, 1); STORE1(c02, 0, 2); STORE1(c03, 0, 3);
    STORE1(c10, 1, 0); STORE1(c11, 1, 1); STORE1(c12, 1, 2); STORE1(c13, 1, 3);
}

// ---------------- rel: R = Q . rel^T ----------------
#define STORE0(CMN, MT, NT) {                                           \
    int r_ = mbase + wm*32 + (MT)*16 + g;                               \
    int c_ = n0 + wn*32 + (NT)*8 + tq*2;                                \
    *(float2*)&g_R[(size_t)r_ * 256 + c_] = make_float2(CMN.x, CMN.y);  \
    *(float2*)&g_R[(size_t)(r_+8) * 256 + c_] = make_float2(CMN.z, CMN.w); }

__global__ __launch_bounds__(256)
void k_rel_mma(const float* __restrict__ rel) {
    __shared__ __align__(16) __nv_bfloat16 sAh[128*SMS], sAl[128*SMS];
    __shared__ __align__(16) __nv_bfloat16 sBh[64*SMS],  sBl[64*SMS];
    int t = threadIdx.x, lane = t & 31, warp = t >> 5;
    int wm = warp >> 1, wn = warp & 1;
    int g = lane >> 2, tq = lane & 3;
    int mt = blockIdx.y;
    int bh = mt >> 3, s0t = (mt & 7) << 7;
    int n0 = blockIdx.x * 64;
    int mbase = bh*1024 + s0t;
    LDM_SETUP();
    float4 c00 = make_float4(0.f,0.f,0.f,0.f), c01 = c00, c02 = c00, c03 = c00;
    float4 c10 = c00, c11 = c00, c12 = c00, c13 = c00;

    for (int k0 = 0; k0 < 64; k0 += 32) {
#pragma unroll
        for (int p = 0; p < 4; p++) {
            int idx = t + p * 256;
            int row = idx >> 3, k4 = (idx & 7) << 2;
            float4 v = *(const float4*)&g_Q[(size_t)(bh*1024 + s0t + row)*64 + k0 + k4];
            int so = row*SMS + k4;
            *(uint32_t*)&sAh[so]     = pack2bf(v.x, v.y);
            *(uint32_t*)&sAh[so + 2] = pack2bf(v.z, v.w);
            *(uint32_t*)&sAl[so]     = pack2bf(bf_res(v.x), bf_res(v.y));
            *(uint32_t*)&sAl[so + 2] = pack2bf(bf_res(v.z), bf_res(v.w));
        }
#pragma unroll
        for (int p = 0; p < 2; p++) {
            int idx = t + p * 256;
            int row = idx >> 3, k4 = (idx & 7) << 2;
            int j = n0 + row;
            float4 w = make_float4(0.f, 0.f, 0.f, 0.f);
            if (j < 255) w = *(const float4*)&rel[(size_t)j * 64 + k0 + k4];
            int so = row*SMS + k4;
            *(uint32_t*)&sBh[so]     = pack2bf(w.x, w.y);
            *(uint32_t*)&sBh[so + 2] = pack2bf(w.z, w.w);
            *(uint32_t*)&sBl[so]     = pack2bf(bf_res(w.x), bf_res(w.y));
            *(uint32_t*)&sBl[so + 2] = pack2bf(bf_res(w.z), bf_res(w.w));
        }
        __syncthreads();
        KSTEP(0);
        KSTEP(16);
        __syncthreads();
    }
    STORE0(c00, 0, 0); STORE0(c01, 0, 1); STORE0(c02, 0, 2); STORE0(c03, 0, 3);
    STORE0(c10, 1, 0); STORE0(c11, 1, 1); STORE0(c12, 1, 2); STORE0(c13, 1, 3);
}

// ---------------- repack qkv -> Q[bh][s][d], K[bh][s][d], Vt[bh][d][s] ----------------
__global__ __launch_bounds__(256)
void k_repack() {
    __shared__ float smem[64][68];
    int t = threadIdx.x;
    int c0 = blockIdx.x * 64, s0 = blockIdx.y * 64, b = blockIdx.z;
#pragma unroll
    for (int p = 0; p < 4; p++) {
        int lin = t + p * 256;
        int s = lin >> 4, c4 = (lin & 15) << 2;
        *(float4*)&smem[s][c4] = *(const float4*)&g_qkv[(size_t)(b*1024 + s0 + s)*N3 + c0 + c4];
    }
    __syncthreads();
    int chunk = c0 >> 10;
    int cw = c0 & 1023;
    int dB = cw >> 4;
    if (chunk < 2) {
        float* out = (chunk == 0) ? g_Q : g_K;   // [bh][s][d]
#pragma unroll
        for (int p = 0; p < 4; p++) {
            int w = t + p * 256;
            int h = w >> 6, ss = w & 63;
            float4 v;
            v.x = smem[ss][h]; v.y = smem[ss][16+h]; v.z = smem[ss][32+h]; v.w = smem[ss][48+h];
            *(float4*)&out[((size_t)(b*16 + h)*1024 + s0 + ss)*64 + dB] = v;
        }
    } else {
#pragma unroll
        for (int p = 0; p < 16; p++) {
            int w = t + p * 256;
            int cc = w >> 6, ss = w & 63;
            int d = dB + (cc >> 4), h = cc & 15;
            g_Vt[((size_t)(b*16 + h)*64 + d)*1024 + s0 + ss] = smem[ss][cc];
        }
    }
}

// ---------------- attention: split-bf16 MMA flash kernel (R13, unchanged) ----------------
__global__ __launch_bounds__(256)
void k_attn_mma(const int* __restrict__ mask) {
    __shared__ __align__(16) __nv_bfloat16 sKh[64*72], sKl[64*72];
    __shared__ __align__(16) __nv_bfloat16 sVh[64*72], sVl[64*72];
    __shared__ float sMax[128], sSum[128];
    int t = threadIdx.x, lane = t & 31, warp = t >> 5;
    int wq = warp >> 1, wk = warp & 1;
    int g = lane >> 2, tq = lane & 3;
    int qt = blockIdx.x, bh = blockIdx.y;
    int b = bh >> 4, q0 = qt << 6;
    int qloc = wq*16 + g;
    int qg = q0 + qloc;
    size_t bhq = (size_t)bh * 1024;

    uint4 qh[4], ql[4];
#pragma unroll
    for (int kk = 0; kk < 4; kk++) {
        int cc = kk*16 + tq*2;
        float2 v00 = *(const float2*)&g_Q[(bhq + qg)*64 + cc];
        float2 v10 = *(const float2*)&g_Q[(bhq + qg + 8)*64 + cc];
        float2 v01 = *(const float2*)&g_Q[(bhq + qg)*64 + cc + 8];
        float2 v11 = *(const float2*)&g_Q[(bhq + qg + 8)*64 + cc + 8];
        qh[kk].x = pack2bf(v00.x, v00.y); ql[kk].x = pack2bf(bf_res(v00.x), bf_res(v00.y));
        qh[kk].y = pack2bf(v10.x, v10.y); ql[kk].y = pack2bf(bf_res(v10.x), bf_res(v10.y));
        qh[kk].z = pack2bf(v01.x, v01.y); ql[kk].z = pack2bf(bf_res(v01.x), bf_res(v01.y));
        qh[kk].w = pack2bf(v11.x, v11.y); ql[kk].w = pack2bf(bf_res(v11.x), bf_res(v11.y));
    }

    float4 o[8];
#pragma unroll
    for (int i = 0; i < 8; i++) o[i] = make_float4(0.f, 0.f, 0.f, 0.f);
    float m0 = -INFINITY, m1 = -INFINITY, l0 = 0.f, l1 = 0.f;

    const float* Rq  = g_R + (bhq + qg) * 256;
    const float* Rq8 = g_R + (bhq + qg + 8) * 256;
    const int* Mq  = mask + ((size_t)b*1024 + qg) * 1024;
    const int* Mq8 = mask + ((size_t)b*1024 + qg + 8) * 1024;

    for (int kt = 0; kt < 16; kt++) {
        int ktb = kt * 64;
#pragma unroll
        for (int p = 0; p < 4; p++) {
            int id = t + p * 256;
            int row = id >> 4, c4 = (id & 15) << 2;
            float4 v = *(const float4*)&g_K[(bhq + ktb + row)*64 + c4];
            *(uint32_t*)&sKh[row*72 + c4]     = pack2bf(v.x, v.y);
            *(uint32_t*)&sKh[row*72 + c4 + 2] = pack2bf(v.z, v.w);
            *(uint32_t*)&sKl[row*72 + c4]     = pack2bf(bf_res(v.x), bf_res(v.y));
            *(uint32_t*)&sKl[row*72 + c4 + 2] = pack2bf(bf_res(v.z), bf_res(v.w));
            float4 w = *(const float4*)&g_Vt[((size_t)bh*64 + row)*1024 + ktb + c4];
            *(uint32_t*)&sVh[row*72 + c4]     = pack2bf(w.x, w.y);
            *(uint32_t*)&sVh[row*72 + c4 + 2] = pack2bf(w.z, w.w);
            *(uint32_t*)&sVl[row*72 + c4]     = pack2bf(bf_res(w.x), bf_res(w.y));
            *(uint32_t*)&sVl[row*72 + c4 + 2] = pack2bf(bf_res(w.z), bf_res(w.w));
        }
        __syncthreads();

        float4 s4[4];
#pragma unroll
        for (int i = 0; i < 4; i++) s4[i] = make_float4(0.f, 0.f, 0.f, 0.f);
#pragma unroll
        for (int nt = 0; nt < 4; nt++) {
            int rowb = (wk*32 + nt*8 + g)*72;
#pragma unroll
            for (int kk = 0; kk < 4; kk++) {
                int cc = rowb + kk*16 + tq*2;
                uint32_t b0h = LD32S(sKh, cc), b1h = LD32S(sKh, cc + 8);
                uint32_t b0l = LD32S(sKl, cc), b1l = LD32S(sKl, cc + 8);
                MMA_OP(s4[nt], qh[kk], b0h, b1h);
                MMA_OP(s4[nt], qh[kk], b0l, b1l);
                MMA_OP(s4[nt], ql[kk], b0h, b1h);
            }
        }

        int kb = ktb + wk*32;
#pragma unroll
        for (int nt = 0; nt < 4; nt++) {
            int kg = kb + nt*8 + tq*2;
            int rx = min(127, max(-127, kg - qg)) + 127;
            int ry = min(127, max(-127, kg + 1 - qg)) + 127;
            int rz = min(127, max(-127, kg - qg - 8)) + 127;
            int rw = min(127, max(-127, kg + 1 - qg - 8)) + 127;
            int2 mv0 = *(const int2*)&Mq[kg];
            int2 mv1 = *(const int2*)&Mq8[kg];
            s4[nt].x = (mv0.x == 0) ? -1e8f : 8.f*s4[nt].x + __ldg(&Rq[rx]);
            s4[nt].y = (mv0.y == 0) ? -1e8f : 8.f*s4[nt].y + __ldg(&Rq[ry]);
            s4[nt].z = (mv1.x == 0) ? -1e8f : 8.f*s4[nt].z + __ldg(&Rq8[rz]);
            s4[nt].w = (mv1.y == 0) ? -1e8f : 8.f*s4[nt].w + __ldg(&Rq8[rw]);
        }

        float mg  = fmaxf(fmaxf(s4[0].x, s4[0].y), fmaxf(s4[1].x, s4[1].y));
        mg = fmaxf(mg, fmaxf(fmaxf(s4[2].x, s4[2].y), fmaxf(s4[3].x, s4[3].y)));
        float mg8 = fmaxf(fmaxf(s4[0].z, s4[0].w), fmaxf(s4[1].z, s4[1].w));
        mg8 = fmaxf(mg8, fmaxf(fmaxf(s4[2].z, s4[2].w), fmaxf(s4[3].z, s4[3].w)));
        mg  = fmaxf(mg,  __shfl_xor_sync(0xffffffffu, mg, 1));
        mg  = fmaxf(mg,  __shfl_xor_sync(0xffffffffu, mg, 2));
        mg8 = fmaxf(mg8, __shfl_xor_sync(0xffffffffu, mg8, 1));
        mg8 = fmaxf(mg8, __shfl_xor_sync(0xffffffffu, mg8, 2));
        if (tq == 0) { sMax[wk*64 + qloc] = mg; sMax[wk*64 + qloc + 8] = mg8; }
        __syncthreads();
        float mn0 = fmaxf(m0, fmaxf(sMax[qloc], sMax[64 + qloc]));
        float mn1 = fmaxf(m1, fmaxf(sMax[qloc + 8], sMax[64 + qloc + 8]));
        float cr0 = __expf(m0 - mn0), cr1 = __expf(m1 - mn1);

        float sg = 0.f, sg8 = 0.f;
#pragma unroll
        for (int nt = 0; nt < 4; nt++) {
            s4[nt].x = __expf(s4[nt].x - mn0); s4[nt].y = __expf(s4[nt].y - mn0);
            s4[nt].z = __expf(s4[nt].z - mn1); s4[nt].w = __expf(s4[nt].w - mn1);
            sg  += s4[nt].x + s4[nt].y;
            sg8 += s4[nt].z + s4[nt].w;
        }
        sg  += __shfl_xor_sync(0xffffffffu, sg, 1);  sg  += __shfl_xor_sync(0xffffffffu, sg, 2);
        sg8 += __shfl_xor_sync(0xffffffffu, sg8, 1); sg8 += __shfl_xor_sync(0xffffffffu, sg8, 2);
        if (tq == 0) { sSum[wk*64 + qloc] = sg; sSum[wk*64 + qloc + 8] = sg8; }
        __syncthreads();
        l0 = l0*cr0 + sSum[qloc] + sSum[64 + qloc];
        l1 = l1*cr1 + sSum[qloc + 8] + sSum[64 + qloc + 8];
        m0 = mn0; m1 = mn1;
#pragma unroll
        for (int i = 0; i < 8; i++) { o[i].x *= cr0; o[i].y *= cr0; o[i].z *= cr1; o[i].w *= cr1; }

        uint4 pa0h, pa0l, pa1h, pa1l;
        pa0h.x = pack2bf(s4[0].x, s4[0].y); pa0h.y = pack2bf(s4[0].z, s4[0].w);
        pa0h.z = pack2bf(s4[1].x, s4[1].y); pa0h.w = pack2bf(s4[1].z, s4[1].w);
        pa1h.x = pack2bf(s4[2].x, s4[2].y); pa1h.y = pack2bf(s4[2].z, s4[2].w);
        pa1h.z = pack2bf(s4[3].x, s4[3].y); pa1h.w = pack2bf(s4[3].z, s4[3].w);
        pa0l.x = pack2bf(bf_res(s4[0].x), bf_res(s4[0].y)); pa0l.y = pack2bf(bf_res(s4[0].z), bf_res(s4[0].w));
        pa0l.z = pack2bf(bf_res(s4[1].x), bf_res(s4[1].y)); pa0l.w = pack2bf(bf_res(s4[1].z), bf_res(s4[1].w));
        pa1l.x = pack2bf(bf_res(s4[2].x), bf_res(s4[2].y)); pa1l.y = pack2bf(bf_res(s4[2].z), bf_res(s4[2].w));
        pa1l.z = pack2bf(bf_res(s4[3].x), bf_res(s4[3].y)); pa1l.w = pack2bf(bf_res(s4[3].z), bf_res(s4[3].w));

#pragma unroll
        for (int nt = 0; nt < 8; nt++) {
            int rb = (nt*8 + g)*72 + wk*32;
            {
                int cc = rb + tq*2;
                uint32_t b0h = LD32S(sVh, cc), b1h = LD32S(sVh, cc + 8);
                uint32_t b0l = LD32S(sVl, cc), b1l = LD32S(sVl, cc + 8);
                MMA_OP(o[nt], pa0h, b0h, b1h);
                MMA_OP(o[nt], pa0h, b0l, b1l);
                MMA_OP(o[nt], pa0l, b0h, b1h);
            }
            {
                int cc = rb + 16 + tq*2;
                uint32_t b0h = LD32S(sVh, cc), b1h = LD32S(sVh, cc + 8);
                uint32_t b0l = LD32S(sVl, cc), b1l = LD32S(sVl, cc + 8);
                MMA_OP(o[nt], pa1h, b0h, b1h);
                MMA_OP(o[nt], pa1h, b0l, b1l);
                MMA_OP(o[nt], pa1l, b0h, b1h);
            }
        }
        __syncthreads();
    }

    float* sO = (float*)sKh;
    if (wk == 0) {
#pragma unroll
        for (int nt = 0; nt < 8; nt++) {
            *(float2*)&sO[qloc*64 + nt*8 + tq*2]       = make_float2(o[nt].x, o[nt].y);
            *(float2*)&sO[(qloc + 8)*64 + nt*8 + tq*2] = make_float2(o[nt].z, o[nt].w);
        }
    }
    __syncthreads();
    if (wk == 1) {
        float inv0 = 1.f / l0, inv1 = 1.f / l1;
#pragma unroll
        for (int nt = 0; nt < 8; nt++) {
            float2 a  = *(float2*)&sO[qloc*64 + nt*8 + tq*2];
            float2 a8 = *(float2*)&sO[(qloc + 8)*64 + nt*8 + tq*2];
            *(float2*)&g_AO[(bhq + qg)*64 + nt*8 + tq*2] =
                make_float2((a.x + o[nt].x)*inv0, (a.y + o[nt].y)*inv0);
            *(float2*)&g_AO[(bhq + qg + 8)*64 + nt*8 + tq*2] =
                make_float2((a8.x + o[nt].z)*inv1, (a8.y + o[nt].w)*inv1);
        }
    }
}

extern "C" void kernel_launch(void* const* d_in, const int* in_sizes, int n_in,
                              void* d_out, int out_size) {
    const float* x     = (const float*)d_in[0];
    const int*   mask  = (const int*)  d_in[1];
    const float* w_qkv = (const float*)d_in[2];
    const float* b_qkv = (const float*)d_in[3];
    const float* rel   = (const float*)d_in[4];
    const float* w_out = (const float*)d_in[5];
    const float* b_out = (const float*)d_in[6];
    float* out = (float*)d_out;

    k_gemm1_mma<<<dim3(48, 32), 256>>>(x, w_qkv, b_qkv);
    k_repack   <<<dim3(48, 16, 4), 256>>>();
    k_rel_mma  <<<dim3(4, 512), 256>>>(rel);
    k_attn_mma <<<dim3(16, 64), 256>>>(mask);
    k_gemm2_mma<<<dim3(16, 32), 256>>>(w_out, b_out, out);
}

// round 16
// speedup vs baseline: 1.6246x; 1.0019x over previous
#include <cuda_runtime.h>
#include <cuda_bf16.h>
#include <math.h>
#include <stdint.h>

#define NB 4
#define NS 1024
#define NH 16
#define HD 64
#define BH (NB*NH)
#define N3 3072

// scratch (fp32 statics only)
__device__ float g_qkv[NB*NS*N3];     // [4096][3072]
__device__ float g_Q[BH*NS*HD];       // [bh][s][d]
__device__ float g_K[BH*NS*HD];       // [bh][s][d]
__device__ float g_Vt[BH*HD*NS];      // [bh][d][s]
__device__ float g_R[BH*NS*256];      // [(bh*1024+q)][256]
__device__ float g_AO[BH*NS*HD];      // [bh][s][d]

// ---------------- split helpers ----------------
__device__ __forceinline__ uint32_t pack2bf(float a, float b) {
    __nv_bfloat162 t = __floats2bfloat162_rn(a, b);
    return *reinterpret_cast<uint32_t*>(&t);
}
__device__ __forceinline__ float bf_res(float a) {
    return a - __bfloat162float(__float2bfloat16(a));
}

// ---------------- shared MMA template ----------------
#define SMS 40
#define ABUF_E (128*SMS)     // 5120 elems per A buffer
#define BBUF_E (64*SMS)      // 2560 elems per B buffer
#define GEMM_SMEM ((2*ABUF_E*2 + 2*BBUF_E*2) * 2)   // 61440 bytes

#define MMA_OP(D, A, B0, B1)                                            \
    asm volatile(                                                       \
        "mma.sync.aligned.m16n8k16.row.col.f32.bf16.bf16.f32 "          \
        "{%0,%1,%2,%3}, {%4,%5,%6,%7}, {%8,%9}, {%0,%1,%2,%3};"         \
        : "+f"(D.x), "+f"(D.y), "+f"(D.z), "+f"(D.w)                    \
        : "r"(A.x), "r"(A.y), "r"(A.z), "r"(A.w), "r"(B0), "r"(B1))

#define LD32S(arr, idx) (*(const uint32_t*)&(arr)[idx])

#define LDM_X4(D, ADDR)                                                 \
    asm volatile("ldmatrix.sync.aligned.m8n8.x4.shared.b16 "            \
        "{%0,%1,%2,%3}, [%4];"                                          \
        : "=r"(D.x), "=r"(D.y), "=r"(D.z), "=r"(D.w) : "r"(ADDR))

#define LDM_SETUP()                                                     \
    uint32_t _ao = (uint32_t)(((wm*32 + (lane & 15))*SMS + (lane >> 4)*8) * 2); \
    uint32_t _bo = (uint32_t)(((wn*32 + (lane & 15))*SMS + (lane >> 4)*8) * 2); \
    uint32_t pA0h = (uint32_t)__cvta_generic_to_shared(sAh) + _ao;      \
    uint32_t pA1h = pA0h + 16*SMS*2;                                    \
    uint32_t pA0l = (uint32_t)__cvta_generic_to_shared(sAl) + _ao;      \
    uint32_t pA1l = pA0l + 16*SMS*2;                                    \
    uint32_t pB0h = (uint32_t)__cvta_generic_to_shared(sBh) + _bo;      \
    uint32_t pB1h = pB0h + 16*SMS*2;                                    \
    uint32_t pB0l = (uint32_t)__cvta_generic_to_shared(sBl) + _bo;      \
    uint32_t pB1l = pB0l + 16*SMS*2;

// B x4 mapping: (x,z) = n-tile0 {b0,b1}; (y,w) = n-tile1. AOFS/BOFS in bytes.
#define KSTEP(KK, AOFS, BOFS) {                                         \
    uint4 a0h, a1h, a0l, a1l, b01h, b23h, b01l, b23l;                   \
    LDM_X4(a0h, pA0h + (AOFS) + (KK)*2); LDM_X4(a1h, pA1h + (AOFS) + (KK)*2); \
    LDM_X4(a0l, pA0l + (AOFS) + (KK)*2); LDM_X4(a1l, pA1l + (AOFS) + (KK)*2); \
    LDM_X4(b01h, pB0h + (BOFS) + (KK)*2); LDM_X4(b23h, pB1h + (BOFS) + (KK)*2); \
    LDM_X4(b01l, pB0l + (BOFS) + (KK)*2); LDM_X4(b23l, pB1l + (BOFS) + (KK)*2); \
    MMA_OP(c00, a0h, b01h.x, b01h.z); MMA_OP(c00, a0h, b01l.x, b01l.z); MMA_OP(c00, a0l, b01h.x, b01h.z); \
    MMA_OP(c10, a1h, b01h.x, b01h.z); MMA_OP(c10, a1h, b01l.x, b01l.z); MMA_OP(c10, a1l, b01h.x, b01h.z); \
    MMA_OP(c01, a0h, b01h.y, b01h.w); MMA_OP(c01, a0h, b01l.y, b01l.w); MMA_OP(c01, a0l, b01h.y, b01h.w); \
    MMA_OP(c11, a1h, b01h.y, b01h.w); MMA_OP(c11, a1h, b01l.y, b01l.w); MMA_OP(c11, a1l, b01h.y, b01h.w); \
    MMA_OP(c02, a0h, b23h.x, b23h.z); MMA_OP(c02, a0h, b23l.x, b23l.z); MMA_OP(c02, a0l, b23h.x, b23h.z); \
    MMA_OP(c12, a1h, b23h.x, b23h.z); MMA_OP(c12, a1h, b23l.x, b23l.z); MMA_OP(c12, a1l, b23h.x, b23h.z); \
    MMA_OP(c03, a0h, b23h.y, b23h.w); MMA_OP(c03, a0h, b23l.y, b23l.w); MMA_OP(c03, a0l, b23h.y, b23h.w); \
    MMA_OP(c13, a1h, b23h.y, b23h.w); MMA_OP(c13, a1h, b23l.y, b23l.w); MMA_OP(c13, a1l, b23h.y, b23h.w); \
}

// A-stage store: va0..va3 -> rows aRow+{0,32,64,96}; B-stage: vb0,vb1 [k][n]-transposed
#define STORE_A(BUF) {                                                  \
    int ao_ = (BUF)*ABUF_E;                                             \
    int so_ = ao_ + aRow*SMS + aK4;                                     \
    *(uint32_t*)&sAh[so_]     = pack2bf(va0.x, va0.y);                  \
    *(uint32_t*)&sAh[so_ + 2] = pack2bf(va0.z, va0.w);                  \
    *(uint32_t*)&sAl[so_]     = pack2bf(bf_res(va0.x), bf_res(va0.y));  \
    *(uint32_t*)&sAl[so_ + 2] = pack2bf(bf_res(va0.z), bf_res(va0.w));  \
    so_ += 32*SMS;                                                      \
    *(uint32_t*)&sAh[so_]     = pack2bf(va1.x, va1.y);                  \
    *(uint32_t*)&sAh[so_ + 2] = pack2bf(va1.z, va1.w);                  \
    *(uint32_t*)&sAl[so_]     = pack2bf(bf_res(va1.x), bf_res(va1.y));  \
    *(uint32_t*)&sAl[so_ + 2] = pack2bf(bf_res(va1.z), bf_res(va1.w));  \
    so_ += 32*SMS;                                                      \
    *(uint32_t*)&sAh[so_]     = pack2bf(va2.x, va2.y);                  \
    *(uint32_t*)&sAh[so_ + 2] = pack2bf(va2.z, va2.w);                  \
    *(uint32_t*)&sAl[so_]     = pack2bf(bf_res(va2.x), bf_res(va2.y));  \
    *(uint32_t*)&sAl[so_ + 2] = pack2bf(bf_res(va2.z), bf_res(va2.w));  \
    so_ += 32*SMS;                                                      \
    *(uint32_t*)&sAh[so_]     = pack2bf(va3.x, va3.y);                  \
    *(uint32_t*)&sAh[so_ + 2] = pack2bf(va3.z, va3.w);                  \
    *(uint32_t*)&sAl[so_]     = pack2bf(bf_res(va3.x), bf_res(va3.y));  \
    *(uint32_t*)&sAl[so_ + 2] = pack2bf(bf_res(va3.z), bf_res(va3.w)); }

#define STORE_BT(BUF) {                                                 \
    int bo_ = (BUF)*BBUF_E;                                             \
    sBh[bo_ + (bN4+0)*SMS + bKr] = __float2bfloat16(vb0.x);             \
    sBh[bo_ + (bN4+1)*SMS + bKr] = __float2bfloat16(vb0.y);             \
    sBh[bo_ + (bN4+2)*SMS + bKr] = __float2bfloat16(vb0.z);             \
    sBh[bo_ + (bN4+3)*SMS + bKr] = __float2bfloat16(vb0.w);             \
    sBl[bo_ + (bN4+0)*SMS + bKr] = __float2bfloat16(bf_res(vb0.x));     \
    sBl[bo_ + (bN4+1)*SMS + bKr] = __float2bfloat16(bf_res(vb0.y));     \
    sBl[bo_ + (bN4+2)*SMS + bKr] = __float2bfloat16(bf_res(vb0.z));     \
    sBl[bo_ + (bN4+3)*SMS + bKr] = __float2bfloat16(bf_res(vb0.w));     \
    sBh[bo_ + (bN4+0)*SMS + bKr+16] = __float2bfloat16(vb1.x);          \
    sBh[bo_ + (bN4+1)*SMS + bKr+16] = __float2bfloat16(vb1.y);          \
    sBh[bo_ + (bN4+2)*SMS + bKr+16] = __float2bfloat16(vb1.z);          \
    sBh[bo_ + (bN4+3)*SMS + bKr+16] = __float2bfloat16(vb1.w);          \
    sBl[bo_ + (bN4+0)*SMS + bKr+16] = __float2bfloat16(bf_res(vb1.x));  \
    sBl[bo_ + (bN4+1)*SMS + bKr+16] = __float2bfloat16(bf_res(vb1.y));  \
    sBl[bo_ + (bN4+2)*SMS + bKr+16] = __float2bfloat16(bf_res(vb1.z));  \
    sBl[bo_ + (bN4+3)*SMS + bKr+16] = __float2bfloat16(bf_res(vb1.w)); }

// B stage in [n-row][k] form (rel kernel): vb0,vb1 -> rows bRow,bRow+32
#define STORE_BR(BUF) {                                                 \
    int bo_ = (BUF)*BBUF_E;                                             \
    int so_ = bo_ + bRow*SMS + bK4;                                     \
    *(uint32_t*)&sBh[so_]     = pack2bf(vb0.x, vb0.y);                  \
    *(uint32_t*)&sBh[so_ + 2] = pack2bf(vb0.z, vb0.w);                  \
    *(uint32_t*)&sBl[so_]     = pack2bf(bf_res(vb0.x), bf_res(vb0.y));  \
    *(uint32_t*)&sBl[so_ + 2] = pack2bf(bf_res(vb0.z), bf_res(vb0.w));  \
    so_ += 32*SMS;                                                      \
    *(uint32_t*)&sBh[so_]     = pack2bf(vb1.x, vb1.y);                  \
    *(uint32_t*)&sBh[so_ + 2] = pack2bf(vb1.z, vb1.w);                  \
    *(uint32_t*)&sBl[so_]     = pack2bf(bf_res(vb1.x), bf_res(vb1.y));  \
    *(uint32_t*)&sBl[so_ + 2] = pack2bf(bf_res(vb1.z), bf_res(vb1.w)); }

#define GEMM_PTRS()                                                     \
    extern __shared__ __align__(16) __nv_bfloat16 smem[];               \
    __nv_bfloat16* sAh = smem;                                          \
    __nv_bfloat16* sAl = smem + 2*ABUF_E;                               \
    __nv_bfloat16* sBh = smem + 4*ABUF_E;                               \
    __nv_bfloat16* sBl = smem + 4*ABUF_E + 2*BBUF_E;

#define STORE1(CMN, MT, NT) {                                           \
    int r_ = m0 + wm*32 + (MT)*16 + g;                                  \
    int c_ = n0 + wn*32 + (NT)*8 + tq*2;                                \
    float b0_ = bias[c_], b1_ = bias[c_+1];                             \
    *(float2*)&C[(size_t)r_ * N + c_] = make_float2(CMN.x + b0_, CMN.y + b1_); \
    *(float2*)&C[(size_t)(r_+8) * N + c_] = make_float2(CMN.z + b0_, CMN.w + b1_); }

// ---------------- GEMM1: qkv = x @ w_qkv + b (double-buffered) ----------------
__global__ __launch_bounds__(256)
void k_gemm1_mma(const float* __restrict__ X, const float* __restrict__ W,
                 const float* __restrict__ bias) {
    const int N = N3, K = 1024;
    GEMM_PTRS();
    float* C = g_qkv;
    int t = threadIdx.x, lane = t & 31, warp = t >> 5;
    int wm = warp >> 1, wn = warp & 1;
    int g = lane >> 2, tq = lane & 3;
    int m0 = blockIdx.y * 128, n0 = blockIdx.x * 64;
    int aRow = t >> 3, aK4 = (t & 7) << 2;
    int bKr = t >> 4, bN4 = (t & 15) << 2;
    LDM_SETUP();
    float4 c00 = make_float4(0.f,0.f,0.f,0.f), c01 = c00, c02 = c00, c03 = c00;
    float4 c10 = c00, c11 = c00, c12 = c00, c13 = c00;
    float4 va0, va1, va2, va3, vb0, vb1;

#define G1_LOAD(K0) {                                                   \
    va0 = *(const float4*)&X[(size_t)(m0 + aRow      ) * K + (K0) + aK4]; \
    va1 = *(const float4*)&X[(size_t)(m0 + aRow + 32 ) * K + (K0) + aK4]; \
    va2 = *(const float4*)&X[(size_t)(m0 + aRow + 64 ) * K + (K0) + aK4]; \
    va3 = *(const float4*)&X[(size_t)(m0 + aRow + 96 ) * K + (K0) + aK4]; \
    vb0 = *(const float4*)&W[(size_t)((K0) + bKr     ) * N + n0 + bN4];   \
    vb1 = *(const float4*)&W[(size_t)((K0) + bKr + 16) * N + n0 + bN4]; }

    G1_LOAD(0);
    STORE_A(0); STORE_BT(0);
    __syncthreads();
    for (int k0 = 0; k0 < K; k0 += 32) {
        int cur = (k0 >> 5) & 1;
        if (k0 + 32 < K) G1_LOAD(k0 + 32);
        int aofs = cur * ABUF_E * 2, bofs = cur * BBUF_E * 2;
        KSTEP(0, aofs, bofs);
        KSTEP(16, aofs, bofs);
        if (k0 + 32 < K) { STORE_A(cur ^ 1); STORE_BT(cur ^ 1); }
        __syncthreads();
    }
    STORE1(c00, 0, 0); STORE1(c01, 0, 1); STORE1(c02, 0, 2); STORE1(c03, 0, 3);
    STORE1(c10, 1, 0); STORE1(c11, 1, 1); STORE1(c12, 1, 2); STORE1(c13, 1, 3);
#undef G1_LOAD
}

// ---------------- GEMM2: out = AO(hidden) @ w_out + b (double-buffered) ----------------
__global__ __launch_bounds__(256)
void k_gemm2_mma(const float* __restrict__ W, const float* __restrict__ bias,
                 float* __restrict__ C) {
    const int N = 1024, K = 1024;
    GEMM_PTRS();
    int t = threadIdx.x, lane = t & 31, warp = t >> 5;
    int wm = warp >> 1, wn = warp & 1;
    int g = lane >> 2, tq = lane & 3;
    int m0 = blockIdx.y * 128, n0 = blockIdx.x * 64;
    int aRow = t >> 3, aK4 = (t & 7) << 2;
    int bKr = t >> 4, bN4 = (t & 15) << 2;
    LDM_SETUP();
    float4 c00 = make_float4(0.f,0.f,0.f,0.f), c01 = c00, c02 = c00, c03 = c00;
    float4 c10 = c00, c11 = c00, c12 = c00, c13 = c00;
    float4 va0, va1, va2, va3, vb0, vb1;

#define G2_LOADA1(RO, K0, DST) {                                        \
    int m_ = m0 + aRow + (RO);                                          \
    int ba_ = m_ >> 10, sa_ = m_ & 1023;                                \
    DST = *(const float4*)&g_AO[((size_t)(ba_*16 + ((K0) >> 6))*1024 + sa_)*64 + ((K0) & 63) + aK4]; }
#define G2_LOAD(K0) {                                                   \
    G2_LOADA1(0,  K0, va0); G2_LOADA1(32, K0, va1);                     \
    G2_LOADA1(64, K0, va2); G2_LOADA1(96, K0, va3);                     \
    int r0_ = (K0) + bKr, r1_ = (K0) + bKr + 16;                        \
    int wr0_ = ((r0_ & 63) << 4) + (r0_ >> 6);                          \
    int wr1_ = ((r1_ & 63) << 4) + (r1_ >> 6);                          \
    vb0 = *(const float4*)&W[(size_t)wr0_ * N + n0 + bN4];              \
    vb1 = *(const float4*)&W[(size_t)wr1_ * N + n0 + bN4]; }

    G2_LOAD(0);
    STORE_A(0); STORE_BT(0);
    __syncthreads();
    for (int k0 = 0; k0 < K; k0 += 32) {
        int cur = (k0 >> 5) & 1;
        if (k0 + 32 < K) G2_LOAD(k0 + 32);
        int aofs = cur * ABUF_E * 2, bofs = cur * BBUF_E * 2;
        KSTEP(0, aofs, bofs);
        KSTEP(16, aofs, bofs);
        if (k0 + 32 < K) { STORE_A(cur ^ 1); STORE_BT(cur ^ 1); }
        __syncthreads();
    }
    STORE1(c00, 0, 0); STORE1(c01, 0, 1); STORE1(c02, 0, 2); STORE1(c03, 0, 3);
    STORE1(c10, 1, 0); STORE1(c11, 1, 1); STORE1(c12, 1, 2); STORE1(c13, 1, 3);
#undef G2_LOAD
#undef G2_LOADA1
}

// ---------------- rel: R = Q . rel^T (double-buffered, K=64, no bias) ----------------
#define STORE0(CMN, MT, NT) {                                           \
    int r_ = mbase + wm*32 + (MT)*16 + g;                               \
    int c_ = n0 + wn*32 + (NT)*8 + tq*2;                                \
    *(float2*)&g_R[(size_t)r_ * 256 + c_] = make_float2(CMN.x, CMN.y);  \
    *(float2*)&g_R[(size_t)(r_+8) * 256 + c_] = make_float2(CMN.z, CMN.w); }

__global__ __launch_bounds__(256)
void k_rel_mma(const float* __restrict__ rel) {
    GEMM_PTRS();
    int t = threadIdx.x, lane = t & 31, warp = t >> 5;
    int wm = warp >> 1, wn = warp & 1;
    int g = lane >> 2, tq = lane & 3;
    int mt = blockIdx.y;
    int bh = mt >> 3, s0t = (mt & 7) << 7;
    int n0 = blockIdx.x * 64;
    int mbase = bh*1024 + s0t;
    int aRow = t >> 3, aK4 = (t & 7) << 2;
    int bRow = t >> 3, bK4 = (t & 7) << 2;
    LDM_SETUP();
    float4 c00 = make_float4(0.f,0.f,0.f,0.f), c01 = c00, c02 = c00, c03 = c00;
    float4 c10 = c00, c11 = c00, c12 = c00, c13 = c00;
    float4 va0, va1, va2, va3, vb0, vb1;

#define GR_LOAD(K0) {                                                   \
    va0 = *(const float4*)&g_Q[(size_t)(bh*1024 + s0t + aRow      )*64 + (K0) + aK4]; \
    va1 = *(const float4*)&g_Q[(size_t)(bh*1024 + s0t + aRow + 32 )*64 + (K0) + aK4]; \
    va2 = *(const float4*)&g_Q[(size_t)(bh*1024 + s0t + aRow + 64 )*64 + (K0) + aK4]; \
    va3 = *(const float4*)&g_Q[(size_t)(bh*1024 + s0t + aRow + 96 )*64 + (K0) + aK4]; \
    int j0_ = n0 + bRow, j1_ = n0 + bRow + 32;                          \
    vb0 = make_float4(0.f, 0.f, 0.f, 0.f); vb1 = vb0;                   \
    if (j0_ < 255) vb0 = *(const float4*)&rel[(size_t)j0_ * 64 + (K0) + bK4]; \
    if (j1_ < 255) vb1 = *(const float4*)&rel[(size_t)j1_ * 64 + (K0) + bK4]; }

    GR_LOAD(0);
    STORE_A(0); STORE_BR(0);
    __syncthreads();
    for (int k0 = 0; k0 < 64; k0 += 32) {
        int cur = (k0 >> 5) & 1;
        if (k0 + 32 < 64) GR_LOAD(k0 + 32);
        int aofs = cur * ABUF_E * 2, bofs = cur * BBUF_E * 2;
        KSTEP(0, aofs, bofs);
        KSTEP(16, aofs, bofs);
        if (k0 + 32 < 64) { STORE_A(cur ^ 1); STORE_BR(cur ^ 1); }
        __syncthreads();
    }
    STORE0(c00, 0, 0); STORE0(c01, 0, 1); STORE0(c02, 0, 2); STORE0(c03, 0, 3);
    STORE0(c10, 1, 0); STORE0(c11, 1, 1); STORE0(c12, 1, 2); STORE0(c13, 1, 3);
#undef GR_LOAD
}

// ---------------- repack qkv -> Q[bh][s][d], K[bh][s][d], Vt[bh][d][s] ----------------
__global__ __launch_bounds__(256)
void k_repack() {
    __shared__ float smem[64][68];
    int t = threadIdx.x;
    int c0 = blockIdx.x * 64, s0 = blockIdx.y * 64, b = blockIdx.z;
#pragma unroll
    for (int p = 0; p < 4; p++) {
        int lin = t + p * 256;
        int s = lin >> 4, c4 = (lin & 15) << 2;
        *(float4*)&smem[s][c4] = *(const float4*)&g_qkv[(size_t)(b*1024 + s0 + s)*N3 + c0 + c4];
    }
    __syncthreads();
    int chunk = c0 >> 10;
    int cw = c0 & 1023;
    int dB = cw >> 4;
    if (chunk < 2) {
        float* out = (chunk == 0) ? g_Q : g_K;
#pragma unroll
        for (int p = 0; p < 4; p++) {
            int w = t + p * 256;
            int h = w >> 6, ss = w & 63;
            float4 v;
            v.x = smem[ss][h]; v.y = smem[ss][16+h]; v.z = smem[ss][32+h]; v.w = smem[ss][48+h];
            *(float4*)&out[((size_t)(b*16 + h)*1024 + s0 + ss)*64 + dB] = v;
        }
    } else {
#pragma unroll
        for (int p = 0; p < 16; p++) {
            int w = t + p * 256;
            int cc = w >> 6, ss = w & 63;
            int d = dB + (cc >> 4), h = cc & 15;
            g_Vt[((size_t)(b*16 + h)*64 + d)*1024 + s0 + ss] = smem[ss][cc];
        }
    }
}

// ---------------- attention: split-bf16 MMA flash kernel (R15, unchanged) ----------------
__global__ __launch_bounds__(256)
void k_attn_mma(const int* __restrict__ mask) {
    __shared__ __align__(16) __nv_bfloat16 sKh[64*72], sKl[64*72];
    __shared__ __align__(16) __nv_bfloat16 sVh[64*72], sVl[64*72];
    __shared__ float sMax[128], sSum[128];
    int t = threadIdx.x, lane = t & 31, warp = t >> 5;
    int wq = warp >> 1, wk = warp & 1;
    int g = lane >> 2, tq = lane & 3;
    int qt = blockIdx.x, bh = blockIdx.y;
    int b = bh >> 4, q0 = qt << 6;
    int qloc = wq*16 + g;
    int qg = q0 + qloc;
    size_t bhq = (size_t)bh * 1024;

    uint4 qh[4], ql[4];
#pragma unroll
    for (int kk = 0; kk < 4; kk++) {
        int cc = kk*16 + tq*2;
        float2 v00 = *(const float2*)&g_Q[(bhq + qg)*64 + cc];
        float2 v10 = *(const float2*)&g_Q[(bhq + qg + 8)*64 + cc];
        float2 v01 = *(const float2*)&g_Q[(bhq + qg)*64 + cc + 8];
        float2 v11 = *(const float2*)&g_Q[(bhq + qg + 8)*64 + cc + 8];
        qh[kk].x = pack2bf(v00.x, v00.y); ql[kk].x = pack2bf(bf_res(v00.x), bf_res(v00.y));
        qh[kk].y = pack2bf(v10.x, v10.y); ql[kk].y = pack2bf(bf_res(v10.x), bf_res(v10.y));
        qh[kk].z = pack2bf(v01.x, v01.y); ql[kk].z = pack2bf(bf_res(v01.x), bf_res(v01.y));
        qh[kk].w = pack2bf(v11.x, v11.y); ql[kk].w = pack2bf(bf_res(v11.x), bf_res(v11.y));
    }

    float4 o[8];
#pragma unroll
    for (int i = 0; i < 8; i++) o[i] = make_float4(0.f, 0.f, 0.f, 0.f);
    float m0 = -INFINITY, m1 = -INFINITY, l0 = 0.f, l1 = 0.f;

    const float* Rq  = g_R + (bhq + qg) * 256;
    const float* Rq8 = g_R + (bhq + qg + 8) * 256;
    const int* Mq  = mask + ((size_t)b*1024 + qg) * 1024;
    const int* Mq8 = mask + ((size_t)b*1024 + qg + 8) * 1024;

    for (int kt = 0; kt < 16; kt++) {
        int ktb = kt * 64;
#pragma unroll
        for (int p = 0; p < 4; p++) {
            int id = t + p * 256;
            int row = id >> 4, c4 = (id & 15) << 2;
            float4 v = *(const float4*)&g_K[(bhq + ktb + row)*64 + c4];
            *(uint32_t*)&sKh[row*72 + c4]     = pack2bf(v.x, v.y);
            *(uint32_t*)&sKh[row*72 + c4 + 2] = pack2bf(v.z, v.w);
            *(uint32_t*)&sKl[row*72 + c4]     = pack2bf(bf_res(v.x), bf_res(v.y));
            *(uint32_t*)&sKl[row*72 + c4 + 2] = pack2bf(bf_res(v.z), bf_res(v.w));
            float4 w = *(const float4*)&g_Vt[((size_t)bh*64 + row)*1024 + ktb + c4];
            *(uint32_t*)&sVh[row*72 + c4]     = pack2bf(w.x, w.y);
            *(uint32_t*)&sVh[row*72 + c4 + 2] = pack2bf(w.z, w.w);
            *(uint32_t*)&sVl[row*72 + c4]     = pack2bf(bf_res(w.x), bf_res(w.y));
            *(uint32_t*)&sVl[row*72 + c4 + 2] = pack2bf(bf_res(w.z), bf_res(w.w));
        }
        __syncthreads();

        float4 s4[4];
#pragma unroll
        for (int i = 0; i < 4; i++) s4[i] = make_float4(0.f, 0.f, 0.f, 0.f);
#pragma unroll
        for (int nt = 0; nt < 4; nt++) {
            int rowb = (wk*32 + nt*8 + g)*72;
#pragma unroll
            for (int kk = 0; kk < 4; kk++) {
                int cc = rowb + kk*16 + tq*2;
                uint32_t b0h = LD32S(sKh, cc), b1h = LD32S(sKh, cc + 8);
                uint32_t b0l = LD32S(sKl, cc), b1l = LD32S(sKl, cc + 8);
                MMA_OP(s4[nt], qh[kk], b0h, b1h);
                MMA_OP(s4[nt], qh[kk], b0l, b1l);
                MMA_OP(s4[nt], ql[kk], b0h, b1h);
            }
        }

        int kb = ktb + wk*32;
#pragma unroll
        for (int nt = 0; nt < 4; nt++) {
            int kg = kb + nt*8 + tq*2;
            int rx = min(127, max(-127, kg - qg)) + 127;
            int ry = min(127, max(-127, kg + 1 - qg)) + 127;
            int rz = min(127, max(-127, kg - qg - 8)) + 127;
            int rw = min(127, max(-127, kg + 1 - qg - 8)) + 127;
            int2 mv0 = *(const int2*)&Mq[kg];
            int2 mv1 = *(const int2*)&Mq8[kg];
            s4[nt].x = (mv0.x == 0) ? -1e8f : 8.f*s4[nt].x + __ldg(&Rq[rx]);
            s4[nt].y = (mv0.y == 0) ? -1e8f : 8.f*s4[nt].y + __ldg(&Rq[ry]);
            s4[nt].z = (mv1.x == 0) ? -1e8f : 8.f*s4[nt].z + __ldg(&Rq8[rz]);
            s4[nt].w = (mv1.y == 0) ? -1e8f : 8.f*s4[nt].w + __ldg(&Rq8[rw]);
        }

        float mg  = fmaxf(fmaxf(s4[0].x, s4[0].y), fmaxf(s4[1].x, s4[1].y));
        mg = fmaxf(mg, fmaxf(fmaxf(s4[2].x, s4[2].y), fmaxf(s4[3].x, s4[3].y)));
        float mg8 = fmaxf(fmaxf(s4[0].z, s4[0].w), fmaxf(s4[1].z, s4[1].w));
        mg8 = fmaxf(mg8, fmaxf(fmaxf(s4[2].z, s4[2].w), fmaxf(s4[3].z, s4[3].w)));
        mg  = fmaxf(mg,  __shfl_xor_sync(0xffffffffu, mg, 1));
        mg  = fmaxf(mg,  __shfl_xor_sync(0xffffffffu, mg, 2));
        mg8 = fmaxf(mg8, __shfl_xor_sync(0xffffffffu, mg8, 1));
        mg8 = fmaxf(mg8, __shfl_xor_sync(0xffffffffu, mg8, 2));
        if (tq == 0) { sMax[wk*64 + qloc] = mg; sMax[wk*64 + qloc + 8] = mg8; }
        __syncthreads();
        float mn0 = fmaxf(m0, fmaxf(sMax[qloc], sMax[64 + qloc]));
        float mn1 = fmaxf(m1, fmaxf(sMax[qloc + 8], sMax[64 + qloc + 8]));
        float cr0 = __expf(m0 - mn0), cr1 = __expf(m1 - mn1);

        float sg = 0.f, sg8 = 0.f;
#pragma unroll
        for (int nt = 0; nt < 4; nt++) {
            s4[nt].x = __expf(s4[nt].x - mn0); s4[nt].y = __expf(s4[nt].y - mn0);
            s4[nt].z = __expf(s4[nt].z - mn1); s4[nt].w = __expf(s4[nt].w - mn1);
            sg  += s4[nt].x + s4[nt].y;
            sg8 += s4[nt].z + s4[nt].w;
        }
        sg  += __shfl_xor_sync(0xffffffffu, sg, 1);  sg  += __shfl_xor_sync(0xffffffffu, sg, 2);
        sg8 += __shfl_xor_sync(0xffffffffu, sg8, 1); sg8 += __shfl_xor_sync(0xffffffffu, sg8, 2);
        if (tq == 0) { sSum[wk*64 + qloc] = sg; sSum[wk*64 + qloc + 8] = sg8; }
        __syncthreads();
        l0 = l0*cr0 + sSum[qloc] + sSum[64 + qloc];
        l1 = l1*cr1 + sSum[qloc + 8] + sSum[64 + qloc + 8];
        m0 = mn0; m1 = mn1;
#pragma unroll
        for (int i = 0; i < 8; i++) { o[i].x *= cr0; o[i].y *= cr0; o[i].z *= cr1; o[i].w *= cr1; }

        uint4 pa0h, pa0l, pa1h, pa1l;
        pa0h.x = pack2bf(s4[0].x, s4[0].y); pa0h.y = pack2bf(s4[0].z, s4[0].w);
        pa0h.z = pack2bf(s4[1].x, s4[1].y); pa0h.w = pack2bf(s4[1].z, s4[1].w);
        pa1h.x = pack2bf(s4[2].x, s4[2].y); pa1h.y = pack2bf(s4[2].z, s4[2].w);
        pa1h.z = pack2bf(s4[3].x, s4[3].y); pa1h.w = pack2bf(s4[3].z, s4[3].w);
        pa0l.x = pack2bf(bf_res(s4[0].x), bf_res(s4[0].y)); pa0l.y = pack2bf(bf_res(s4[0].z), bf_res(s4[0].w));
        pa0l.z = pack2bf(bf_res(s4[1].x), bf_res(s4[1].y)); pa0l.w = pack2bf(bf_res(s4[1].z), bf_res(s4[1].w));
        pa1l.x = pack2bf(bf_res(s4[2].x), bf_res(s4[2].y)); pa1l.y = pack2bf(bf_res(s4[2].z), bf_res(s4[2].w));
        pa1l.z = pack2bf(bf_res(s4[3].x), bf_res(s4[3].y)); pa1l.w = pack2bf(bf_res(s4[3].z), bf_res(s4[3].w));

#pragma unroll
        for (int nt = 0; nt < 8; nt++) {
            int rb = (nt*8 + g)*72 + wk*32;
            {
                int cc = rb + tq*2;
                uint32_t b0h = LD32S(sVh, cc), b1h = LD32S(sVh, cc + 8);
                uint32_t b0l = LD32S(sVl, cc), b1l = LD32S(sVl, cc + 8);
                MMA_OP(o[nt], pa0h, b0h, b1h);
                MMA_OP(o[nt], pa0h, b0l, b1l);
                MMA_OP(o[nt], pa0l, b0h, b1h);
            }
            {
                int cc = rb + 16 + tq*2;
                uint32_t b0h = LD32S(sVh, cc), b1h = LD32S(sVh, cc + 8);
                uint32_t b0l = LD32S(sVl, cc), b1l = LD32S(sVl, cc + 8);
                MMA_OP(o[nt], pa1h, b0h, b1h);
                MMA_OP(o[nt], pa1h, b0l, b1l);
                MMA_OP(o[nt], pa1l, b0h, b1h);
            }
        }
        __syncthreads();
    }

    float* sO = (float*)sKh;
    if (wk == 0) {
#pragma unroll
        for (int nt = 0; nt < 8; nt++) {
            *(float2*)&sO[qloc*64 + nt*8 + tq*2]       = make_float2(o[nt].x, o[nt].y);
            *(float2*)&sO[(qloc + 8)*64 + nt*8 + tq*2] = make_float2(o[nt].z, o[nt].w);
        }
    }
    __syncthreads();
    if (wk == 1) {
        float inv0 = 1.f / l0, inv1 = 1.f / l1;
#pragma unroll
        for (int nt = 0; nt < 8; nt++) {
            float2 a  = *(float2*)&sO[qloc*64 + nt*8 + tq*2];
            float2 a8 = *(float2*)&sO[(qloc + 8)*64 + nt*8 + tq*2];
            *(float2*)&g_AO[(bhq + qg)*64 + nt*8 + tq*2] =
                make_float2((a.x + o[nt].x)*inv0, (a.y + o[nt].y)*inv0);
            *(float2*)&g_AO[(bhq + qg + 8)*64 + nt*8 + tq*2] =
                make_float2((a8.x + o[nt].z)*inv1, (a8.y + o[nt].w)*inv1);
        }
    }
}

extern "C" void kernel_launch(void* const* d_in, const int* in_sizes, int n_in,
                              void* d_out, int out_size) {
    const float* x     = (const float*)d_in[0];
    const int*   mask  = (const int*)  d_in[1];
    const float* w_qkv = (const float*)d_in[2];
    const float* b_qkv = (const float*)d_in[3];
    const float* rel   = (const float*)d_in[4];
    const float* w_out = (const float*)d_in[5];
    const float* b_out = (const float*)d_in[6];
    float* out = (float*)d_out;

    static int configured = 0;
    if (!configured) {
        cudaFuncSetAttribute(k_gemm1_mma, cudaFuncAttributeMaxDynamicSharedMemorySize, GEMM_SMEM);
        cudaFuncSetAttribute(k_gemm2_mma, cudaFuncAttributeMaxDynamicSharedMemorySize, GEMM_SMEM);
        cudaFuncSetAttribute(k_rel_mma,   cudaFuncAttributeMaxDynamicSharedMemorySize, GEMM_SMEM);
        configured = 1;
    }

    k_gemm1_mma<<<dim3(48, 32), 256, GEMM_SMEM>>>(x, w_qkv, b_qkv);
    k_repack   <<<dim3(48, 16, 4), 256>>>();
    k_rel_mma  <<<dim3(4, 512), 256, GEMM_SMEM>>>(rel);
    k_attn_mma <<<dim3(16, 64), 256>>>(mask);
    k_gemm2_mma<<<dim3(16, 32), 256, GEMM_SMEM>>>(w_out, b_out, out);
}